// round 1
// baseline (speedup 1.0000x reference)
#include <cuda_runtime.h>
#include <math.h>

#define D_MODEL 1024
#define NUM_HEADS 16
#define HEAD_DIM 64
#define NB 4
#define SEQ 2048
#define M_TOTAL (NB*SEQ)   // 8192

// ---------------- scratch (device globals: no allocation allowed) -------------
__device__ float g_Q[NB*NUM_HEADS*SEQ*HEAD_DIM];   // [B,H,S,Hd]
__device__ float g_K[NB*NUM_HEADS*SEQ*HEAD_DIM];
__device__ float g_V[NB*NUM_HEADS*SEQ*HEAD_DIM];
__device__ float g_ctx[M_TOTAL*D_MODEL];           // [B,S,D]

// =============================================================================
// GEMM: C[M,N] = A[M,K] @ W[N,K]^T + bias[N]
// M=8192, N=1024, K=1024.  BM=BN=128, BK=8, 256 threads, 8x8 per thread,
// double-buffered smem.
// mode 0: write into [B,H,S,Hd] layout (QKV proj). mode 1: row-major C.
// =============================================================================
__global__ void __launch_bounds__(256, 2)
gemm_bias_kernel(const float* __restrict__ A, const float* __restrict__ W,
                 const float* __restrict__ bias, float* __restrict__ C, int mode)
{
    const int K = 1024;
    __shared__ float As[2][8][128];
    __shared__ float Bs[2][8][128];

    const int tid  = threadIdx.x;
    const int bm   = blockIdx.y * 128;
    const int bn   = blockIdx.x * 128;
    const int arow = tid >> 1;
    const int acol = (tid & 1) << 2;
    const int tx   = tid & 15;
    const int ty   = tid >> 4;

    const float* Ap = A + (bm + arow) * K + acol;
    const float* Bp = W + (bn + arow) * K + acol;

    float acc[8][8];
#pragma unroll
    for (int i = 0; i < 8; ++i)
#pragma unroll
        for (int j = 0; j < 8; ++j) acc[i][j] = 0.f;

    float4 a4 = *(const float4*)Ap;
    float4 b4 = *(const float4*)Bp;
    int st = 0;
    As[0][acol+0][arow] = a4.x; As[0][acol+1][arow] = a4.y;
    As[0][acol+2][arow] = a4.z; As[0][acol+3][arow] = a4.w;
    Bs[0][acol+0][arow] = b4.x; Bs[0][acol+1][arow] = b4.y;
    Bs[0][acol+2][arow] = b4.z; Bs[0][acol+3][arow] = b4.w;
    __syncthreads();

    for (int kt = 0; kt < K/8; ++kt) {
        if (kt + 1 < K/8) {
            a4 = *(const float4*)(Ap + (kt+1)*8);
            b4 = *(const float4*)(Bp + (kt+1)*8);
        }
#pragma unroll
        for (int k = 0; k < 8; ++k) {
            float af[8], bf[8];
            *(float4*)&af[0] = *(const float4*)&As[st][k][ty*4];
            *(float4*)&af[4] = *(const float4*)&As[st][k][ty*4+64];
            *(float4*)&bf[0] = *(const float4*)&Bs[st][k][tx*4];
            *(float4*)&bf[4] = *(const float4*)&Bs[st][k][tx*4+64];
#pragma unroll
            for (int i = 0; i < 8; ++i)
#pragma unroll
                for (int j = 0; j < 8; ++j)
                    acc[i][j] += af[i] * bf[j];
        }
        if (kt + 1 < K/8) {
            st ^= 1;
            As[st][acol+0][arow] = a4.x; As[st][acol+1][arow] = a4.y;
            As[st][acol+2][arow] = a4.z; As[st][acol+3][arow] = a4.w;
            Bs[st][acol+0][arow] = b4.x; Bs[st][acol+1][arow] = b4.y;
            Bs[st][acol+2][arow] = b4.z; Bs[st][acol+3][arow] = b4.w;
            __syncthreads();
        }
    }

    // epilogue
#pragma unroll
    for (int i = 0; i < 8; ++i) {
        int m = bm + ty*4 + (i & 3) + ((i >> 2) << 6);
#pragma unroll
        for (int jj = 0; jj < 2; ++jj) {
            int n0 = bn + tx*4 + (jj << 6);
            float4 r;
            r.x = acc[i][jj*4+0] + bias[n0+0];
            r.y = acc[i][jj*4+1] + bias[n0+1];
            r.z = acc[i][jj*4+2] + bias[n0+2];
            r.w = acc[i][jj*4+3] + bias[n0+3];
            if (mode == 0) {
                int b = m >> 11, s = m & 2047;
                int h = n0 >> 6, hd = n0 & 63;
                *(float4*)(C + ((((b*NUM_HEADS + h) << 11) + s) << 6) + hd) = r;
            } else {
                *(float4*)(C + m*1024 + n0) = r;
            }
        }
    }
}

// =============================================================================
// Flash attention. One block: 128 queries of one (b,h). Iterates 32 K/V tiles
// of 64 keys. 256 threads = 16x16 grid; per-thread 8q x 4k scores, 8q x 4d out.
// m/l statistics in registers (replicated across 16-lane groups via shfl).
// smem layouts chosen so every inner-loop read is either a warp-broadcast or a
// conflict-free LDS.128.
// =============================================================================
#define BQ 128
#define BK 64
// smem floats: Qt[64][132] + Kt[64][68] + Vs[64][64] + Pt[64][132]
#define QT_LD 132
#define KT_LD 68
#define PT_LD 132
#define ATTN_SMEM_FLOATS (64*QT_LD + 64*KT_LD + 64*64 + 64*PT_LD)
#define ATTN_SMEM_BYTES  (ATTN_SMEM_FLOATS * 4)

__global__ void __launch_bounds__(256, 2)
attn_kernel(const float* __restrict__ Q, const float* __restrict__ Kg,
            const float* __restrict__ Vg, float* __restrict__ ctx)
{
    extern __shared__ float sm[];
    float* Qt = sm;                       // [d][q] pad 132
    float* Kt = Qt + 64*QT_LD;            // [d][k] pad 68
    float* Vs = Kt + 64*KT_LD;            // [k][d] 64x64
    float* Pt = Vs + 64*64;               // [k][q] pad 132

    const int tid = threadIdx.x;
    const int tx  = tid & 15;
    const int ty  = tid >> 4;
    const int qtile = blockIdx.x;         // 0..15
    const int bh    = blockIdx.y;         // 0..63

    const float* Qbase = Q  + bh*SEQ*HEAD_DIM + qtile*BQ*HEAD_DIM;
    const float* Kbase = Kg + bh*SEQ*HEAD_DIM;
    const float* Vbase = Vg + bh*SEQ*HEAD_DIM;

    // load Q tile 128x64 -> Qt[d][q], fold in 1/sqrt(Hd)=0.125
#pragma unroll
    for (int it = 0; it < 8; ++it) {
        int idx = tid + it*256;           // 0..2047
        int row = idx >> 4;               // q 0..127
        int c4  = idx & 15;
        float4 v4 = *(const float4*)(Qbase + row*64 + c4*4);
        Qt[(c4*4+0)*QT_LD + row] = v4.x * 0.125f;
        Qt[(c4*4+1)*QT_LD + row] = v4.y * 0.125f;
        Qt[(c4*4+2)*QT_LD + row] = v4.z * 0.125f;
        Qt[(c4*4+3)*QT_LD + row] = v4.w * 0.125f;
    }

    float m_i[8], l_i[8], O[8][4];
#pragma unroll
    for (int i = 0; i < 8; ++i) {
        m_i[i] = -1e30f; l_i[i] = 0.f;
#pragma unroll
        for (int j = 0; j < 4; ++j) O[i][j] = 0.f;
    }

    for (int kt = 0; kt < SEQ/BK; ++kt) {
        __syncthreads();   // prior PV done reading Vs/Pt (also covers Qt init)
        const float* Kp = Kbase + kt*BK*HEAD_DIM;
        const float* Vp = Vbase + kt*BK*HEAD_DIM;
#pragma unroll
        for (int it = 0; it < 4; ++it) {
            int idx = tid + it*256;
            int row = idx >> 4;           // 0..63
            int c4  = idx & 15;
            float4 kv = *(const float4*)(Kp + row*64 + c4*4);
            Kt[(c4*4+0)*KT_LD + row] = kv.x;
            Kt[(c4*4+1)*KT_LD + row] = kv.y;
            Kt[(c4*4+2)*KT_LD + row] = kv.z;
            Kt[(c4*4+3)*KT_LD + row] = kv.w;
            float4 vv = *(const float4*)(Vp + row*64 + c4*4);
            *(float4*)(Vs + row*64 + c4*4) = vv;
        }
        __syncthreads();

        // S[8][4] = Q @ K^T  (q rows ty*8.., k cols tx*4..)
        float s[8][4];
#pragma unroll
        for (int i = 0; i < 8; ++i)
#pragma unroll
            for (int j = 0; j < 4; ++j) s[i][j] = 0.f;

#pragma unroll 8
        for (int d = 0; d < 64; ++d) {
            float qf[8], kf[4];
            *(float4*)&qf[0] = *(const float4*)&Qt[d*QT_LD + ty*8];
            *(float4*)&qf[4] = *(const float4*)&Qt[d*QT_LD + ty*8 + 4];
            *(float4*)&kf[0] = *(const float4*)&Kt[d*KT_LD + tx*4];
#pragma unroll
            for (int i = 0; i < 8; ++i)
#pragma unroll
                for (int j = 0; j < 4; ++j)
                    s[i][j] += qf[i] * kf[j];
        }

        // online softmax per row; reduce over the 16 tx lanes
#pragma unroll
        for (int i = 0; i < 8; ++i) {
            float mx = fmaxf(fmaxf(s[i][0], s[i][1]), fmaxf(s[i][2], s[i][3]));
#pragma unroll
            for (int off = 8; off >= 1; off >>= 1)
                mx = fmaxf(mx, __shfl_xor_sync(0xffffffffu, mx, off));
            float m_new = fmaxf(m_i[i], mx);
            float alpha = __expf(m_i[i] - m_new);
            float sum = 0.f;
#pragma unroll
            for (int j = 0; j < 4; ++j) {
                float p = __expf(s[i][j] - m_new);
                s[i][j] = p;
                sum += p;
            }
#pragma unroll
            for (int off = 8; off >= 1; off >>= 1)
                sum += __shfl_xor_sync(0xffffffffu, sum, off);
            l_i[i] = l_i[i]*alpha + sum;
            m_i[i] = m_new;
#pragma unroll
            for (int j = 0; j < 4; ++j) O[i][j] *= alpha;
            // store P transposed: Pt[k][q]
#pragma unroll
            for (int j = 0; j < 4; ++j)
                Pt[(tx*4+j)*PT_LD + ty*8 + i] = s[i][j];
        }
        __syncthreads();

        // O[8][4] += P @ V   (d cols tx*4..)
#pragma unroll 8
        for (int k = 0; k < 64; ++k) {
            float pf[8], vf[4];
            *(float4*)&pf[0] = *(const float4*)&Pt[k*PT_LD + ty*8];
            *(float4*)&pf[4] = *(const float4*)&Pt[k*PT_LD + ty*8 + 4];
            *(float4*)&vf[0] = *(const float4*)&Vs[k*64 + tx*4];
#pragma unroll
            for (int i = 0; i < 8; ++i)
#pragma unroll
                for (int j = 0; j < 4; ++j)
                    O[i][j] += pf[i] * vf[j];
        }
    }

    // write ctx[b][s][h*64+d]
    int b = bh >> 4, h = bh & 15;
#pragma unroll
    for (int i = 0; i < 8; ++i) {
        int q = qtile*BQ + ty*8 + i;
        float inv = 1.f / l_i[i];
        float4 o4;
        o4.x = O[i][0]*inv; o4.y = O[i][1]*inv;
        o4.z = O[i][2]*inv; o4.w = O[i][3]*inv;
        *(float4*)(ctx + ((b << 11) + q)*1024 + h*64 + tx*4) = o4;
    }
}

// =============================================================================
extern "C" void kernel_launch(void* const* d_in, const int* in_sizes, int n_in,
                              void* d_out, int out_size)
{
    (void)in_sizes; (void)n_in; (void)out_size;
    const float* x  = (const float*)d_in[0];
    const float* Wq = (const float*)d_in[1];
    const float* bq = (const float*)d_in[2];
    const float* Wk = (const float*)d_in[3];
    const float* bk = (const float*)d_in[4];
    const float* Wv = (const float*)d_in[5];
    const float* bv = (const float*)d_in[6];
    const float* Wo = (const float*)d_in[7];
    const float* bo = (const float*)d_in[8];
    float* out = (float*)d_out;

    float *Qp, *Kp, *Vp, *Cp;
    cudaGetSymbolAddress((void**)&Qp, g_Q);
    cudaGetSymbolAddress((void**)&Kp, g_K);
    cudaGetSymbolAddress((void**)&Vp, g_V);
    cudaGetSymbolAddress((void**)&Cp, g_ctx);

    cudaFuncSetAttribute(attn_kernel,
                         cudaFuncAttributeMaxDynamicSharedMemorySize,
                         ATTN_SMEM_BYTES);

    dim3 gg(1024/128, 8192/128);   // (8, 64)
    gemm_bias_kernel<<<gg, 256>>>(x, Wq, bq, Qp, 0);
    gemm_bias_kernel<<<gg, 256>>>(x, Wk, bk, Kp, 0);
    gemm_bias_kernel<<<gg, 256>>>(x, Wv, bv, Vp, 0);

    attn_kernel<<<dim3(SEQ/BQ, NB*NUM_HEADS), 256, ATTN_SMEM_BYTES>>>(Qp, Kp, Vp, Cp);

    gemm_bias_kernel<<<gg, 256>>>(Cp, Wo, bo, out, 1);
}

// round 3
// speedup vs baseline: 1.2177x; 1.2177x over previous
#include <cuda_runtime.h>
#include <cuda_bf16.h>
#include <math.h>
#include <stdint.h>

#define D_MODEL 1024
#define NUM_HEADS 16
#define HEAD_DIM 64
#define NB 4
#define SEQ 2048
#define M_TOTAL (NB*SEQ)   // 8192

// ---------------- scratch (device globals: no allocation allowed) -------------
__device__ float g_Q[NB*NUM_HEADS*SEQ*HEAD_DIM];   // [B,H,S,Hd]
__device__ float g_K[NB*NUM_HEADS*SEQ*HEAD_DIM];
__device__ float g_V[NB*NUM_HEADS*SEQ*HEAD_DIM];
__device__ float g_ctx[M_TOTAL*D_MODEL];           // [B,S,D]
__device__ __nv_bfloat16 g_ahi[M_TOTAL*D_MODEL];
__device__ __nv_bfloat16 g_alo[M_TOTAL*D_MODEL];
__device__ __nv_bfloat16 g_whi[4*D_MODEL*D_MODEL];
__device__ __nv_bfloat16 g_wlo[4*D_MODEL*D_MODEL];

// =============================== PTX helpers =================================
__device__ __forceinline__ uint32_t smem_u32(const void* p) {
    uint32_t a;
    asm("{ .reg .u64 t; cvta.to.shared.u64 t, %1; cvt.u32.u64 %0, t; }" : "=r"(a) : "l"(p));
    return a;
}

#define CP16(dst, src) \
    asm volatile("cp.async.cg.shared.global [%0], [%1], 16;" :: "r"(dst), "l"(src))
#define CP_COMMIT() asm volatile("cp.async.commit_group;" ::: "memory")
#define CP_WAIT(N)  asm volatile("cp.async.wait_group %0;" :: "n"(N) : "memory")

#define LDSM4(r, addr) \
    asm volatile("ldmatrix.sync.aligned.m8n8.x4.shared.b16 {%0,%1,%2,%3}, [%4];" \
        : "=r"((r)[0]), "=r"((r)[1]), "=r"((r)[2]), "=r"((r)[3]) : "r"(addr))

#define MMA_BF16(c, a, b) \
    asm volatile("mma.sync.aligned.m16n8k16.row.col.f32.bf16.bf16.f32 " \
        "{%0,%1,%2,%3}, {%4,%5,%6,%7}, {%8,%9}, {%0,%1,%2,%3};" \
        : "+f"((c)[0]), "+f"((c)[1]), "+f"((c)[2]), "+f"((c)[3]) \
        : "r"((a)[0]), "r"((a)[1]), "r"((a)[2]), "r"((a)[3]), \
          "r"((b)[0]), "r"((b)[1]))

// =============================================================================
// bf16-split mma.sync GEMM: C[M,N] = (Ah+Al)[M,K] @ (Wh+Wl)[N,K]^T + bias
// D = Ah*Wh + Ah*Wl + Al*Wh  (lo*lo dropped, ~4e-6 relative)
// BM=BN=128, BK=32, 3-stage cp.async, 8 warps of 64x32 warp-tiles.
// smem tile layout: 128 rows x 40 bf16 (80B padded stride -> ldmatrix
// conflict-free). mode 0: scatter C into [B,H,S,Hd]; mode 1: row-major.
// =============================================================================
#define TSTR   40
#define TILE_B (128*TSTR*2)     // 10240 B
#define STAGE_B (4*TILE_B)      // 40960 B (Ah, Al, Wh, Wl)
#define GSTAGES 3
#define GEMM_SMEM (GSTAGES*STAGE_B)   // 122880 B

__device__ __forceinline__ void gemm_mma_body(
    const __nv_bfloat16* __restrict__ Ah, const __nv_bfloat16* __restrict__ Al,
    const __nv_bfloat16* __restrict__ Wh, const __nv_bfloat16* __restrict__ Wl,
    const float* __restrict__ bias, float* __restrict__ C, int mode)
{
    extern __shared__ char smraw[];
    const uint32_t smb = smem_u32(smraw);
    const int tid  = threadIdx.x;
    const int lane = tid & 31;
    const int wid  = tid >> 5;
    const int wm   = wid & 1;        // 2 M-groups of 64
    const int wn   = wid >> 1;       // 4 N-groups of 32
    const int bm   = blockIdx.y * 128;
    const int bn   = blockIdx.x * 128;

    // loader indices: thread -> (row, 32B chunk pair)
    const int lrow = tid >> 1;       // 0..127
    const int lcol = (tid & 1) * 2;  // 0 or 2 (16B chunks)

    const __nv_bfloat16* gA0 = Ah + (size_t)(bm + lrow) * 1024 + lcol * 8;
    const __nv_bfloat16* gA1 = Al + (size_t)(bm + lrow) * 1024 + lcol * 8;
    const __nv_bfloat16* gW0 = Wh + (size_t)(bn + lrow) * 1024 + lcol * 8;
    const __nv_bfloat16* gW1 = Wl + (size_t)(bn + lrow) * 1024 + lcol * 8;
    const uint32_t dstb = smb + lrow * 80 + lcol * 16;

#define LOAD_STAGE(kt) do { \
        const int _st = (kt) % GSTAGES; \
        const uint32_t _d = dstb + _st * STAGE_B; \
        const int _k0 = (kt) * 32; \
        CP16(_d,                gA0 + _k0); CP16(_d + 16,              gA0 + _k0 + 8); \
        CP16(_d +   TILE_B,     gA1 + _k0); CP16(_d +   TILE_B + 16,   gA1 + _k0 + 8); \
        CP16(_d + 2*TILE_B,     gW0 + _k0); CP16(_d + 2*TILE_B + 16,   gW0 + _k0 + 8); \
        CP16(_d + 3*TILE_B,     gW1 + _k0); CP16(_d + 3*TILE_B + 16,   gW1 + _k0 + 8); \
        CP_COMMIT(); \
    } while (0)

    LOAD_STAGE(0);
    LOAD_STAGE(1);

    float acc[4][4][4];
#pragma unroll
    for (int i = 0; i < 4; ++i)
#pragma unroll
        for (int j = 0; j < 4; ++j)
#pragma unroll
            for (int r = 0; r < 4; ++r) acc[i][j][r] = 0.f;

    // ldmatrix base addresses (bytes): row = lane&15, k-half = lane>>4
    const uint32_t a_base = smb + ((wm*64 + (lane & 15)) * TSTR + (lane >> 4) * 8) * 2;
    const uint32_t b_base = smb + ((wn*32 + (lane & 15)) * TSTR + (lane >> 4) * 8) * 2;

    for (int kt = 0; kt < 32; ++kt) {
        if (kt < 30) { CP_WAIT(1); } else { CP_WAIT(0); }
        __syncthreads();
        if (kt + 2 < 32) LOAD_STAGE(kt + 2);

        const uint32_t stoff = (uint32_t)(kt % GSTAGES) * STAGE_B;
#pragma unroll
        for (int kk = 0; kk < 2; ++kk) {
            const uint32_t ko = stoff + kk * 32;   // +16 elems = +32B
            uint32_t ah[4][4], al[4][4], wh2[2][4], wl2[2][4];
#pragma unroll
            for (int i = 0; i < 4; ++i) {
                LDSM4(ah[i], a_base + ko + i*16*80);
                LDSM4(al[i], a_base + ko + TILE_B + i*16*80);
            }
#pragma unroll
            for (int j = 0; j < 2; ++j) {
                LDSM4(wh2[j], b_base + ko + 2*TILE_B + j*16*80);
                LDSM4(wl2[j], b_base + ko + 3*TILE_B + j*16*80);
            }
#pragma unroll
            for (int mi = 0; mi < 4; ++mi)
#pragma unroll
                for (int nj = 0; nj < 4; ++nj) {
                    uint32_t bh[2] = { wh2[nj>>1][nj&1], wh2[nj>>1][(nj&1)+2] };
                    uint32_t bl[2] = { wl2[nj>>1][nj&1], wl2[nj>>1][(nj&1)+2] };
                    MMA_BF16(acc[mi][nj], ah[mi], bh);
                    MMA_BF16(acc[mi][nj], ah[mi], bl);
                    MMA_BF16(acc[mi][nj], al[mi], bh);
                }
        }
    }

    // epilogue: c0,c1 -> row m, cols n,n+1 ; c2,c3 -> row m+8
#pragma unroll
    for (int mi = 0; mi < 4; ++mi) {
#pragma unroll
        for (int nj = 0; nj < 4; ++nj) {
            const int m0 = bm + wm*64 + mi*16 + (lane >> 2);
            const int n0 = bn + wn*32 + nj*8 + (lane & 3)*2;
            float2 bb = *(const float2*)(bias + n0);
            float2 v0, v1;
            v0.x = acc[mi][nj][0] + bb.x;  v0.y = acc[mi][nj][1] + bb.y;
            v1.x = acc[mi][nj][2] + bb.x;  v1.y = acc[mi][nj][3] + bb.y;
            if (mode == 0) {
                const int h = n0 >> 6, hd = n0 & 63;
                const int b0_ = m0 >> 11, s0 = m0 & 2047;
                const int b1_ = (m0+8) >> 11, s1 = (m0+8) & 2047;
                *(float2*)(C + ((((size_t)(b0_*NUM_HEADS + h) << 11) + s0) << 6) + hd) = v0;
                *(float2*)(C + ((((size_t)(b1_*NUM_HEADS + h) << 11) + s1) << 6) + hd) = v1;
            } else {
                *(float2*)(C + (size_t)m0*1024 + n0) = v0;
                *(float2*)(C + (size_t)(m0+8)*1024 + n0) = v1;
            }
        }
    }
#undef LOAD_STAGE
}

__global__ void __launch_bounds__(256, 1)
gemm_qkv_mma(const __nv_bfloat16* ah, const __nv_bfloat16* al,
             const __nv_bfloat16* wh, const __nv_bfloat16* wl,
             const float* b0, const float* b1, const float* b2,
             float* C0, float* C1, float* C2)
{
    const int z = blockIdx.z;
    const __nv_bfloat16* whz = wh + (size_t)z * D_MODEL * D_MODEL;
    const __nv_bfloat16* wlz = wl + (size_t)z * D_MODEL * D_MODEL;
    const float* bias = (z == 0) ? b0 : (z == 1) ? b1 : b2;
    float* C = (z == 0) ? C0 : (z == 1) ? C1 : C2;
    gemm_mma_body(ah, al, whz, wlz, bias, C, 0);
}

__global__ void __launch_bounds__(256, 1)
gemm_out_mma(const __nv_bfloat16* ah, const __nv_bfloat16* al,
             const __nv_bfloat16* wh, const __nv_bfloat16* wl,
             const float* bias, float* C)
{
    gemm_mma_body(ah, al, wh + (size_t)3*D_MODEL*D_MODEL,
                  wl + (size_t)3*D_MODEL*D_MODEL, bias, C, 1);
}

// ======================= fp32 -> bf16 hi/lo split =============================
__global__ void __launch_bounds__(256)
split_kernel(const float* __restrict__ in, __nv_bfloat16* __restrict__ hi,
             __nv_bfloat16* __restrict__ lo, int n4)
{
    int i = blockIdx.x * 256 + threadIdx.x;
    if (i >= n4) return;
    float4 v = ((const float4*)in)[i];
    __nv_bfloat16 hx = __float2bfloat16_rn(v.x);
    __nv_bfloat16 hy = __float2bfloat16_rn(v.y);
    __nv_bfloat16 hz = __float2bfloat16_rn(v.z);
    __nv_bfloat16 hw = __float2bfloat16_rn(v.w);
    float lx = v.x - __bfloat162float(hx);
    float ly = v.y - __bfloat162float(hy);
    float lz = v.z - __bfloat162float(hz);
    float lw = v.w - __bfloat162float(hw);
    __nv_bfloat162* hp = (__nv_bfloat162*)hi;
    __nv_bfloat162* lp = (__nv_bfloat162*)lo;
    hp[2*i+0] = __nv_bfloat162(hx, hy);
    hp[2*i+1] = __nv_bfloat162(hz, hw);
    lp[2*i+0] = __floats2bfloat162_rn(lx, ly);
    lp[2*i+1] = __floats2bfloat162_rn(lz, lw);
}

// =============================================================================
// Flash attention (verified fp32 SIMT from R1; tensorized next round)
// =============================================================================
#define BQ 128
#define BK 64
#define QT_LD 132
#define KT_LD 68
#define PT_LD 132
#define ATTN_SMEM_FLOATS (64*QT_LD + 64*KT_LD + 64*64 + 64*PT_LD)
#define ATTN_SMEM_BYTES  (ATTN_SMEM_FLOATS * 4)

__global__ void __launch_bounds__(256, 2)
attn_kernel(const float* __restrict__ Q, const float* __restrict__ Kg,
            const float* __restrict__ Vg, float* __restrict__ ctx)
{
    extern __shared__ float sm[];
    float* Qt = sm;
    float* Kt = Qt + 64*QT_LD;
    float* Vs = Kt + 64*KT_LD;
    float* Pt = Vs + 64*64;

    const int tid = threadIdx.x;
    const int tx  = tid & 15;
    const int ty  = tid >> 4;
    const int qtile = blockIdx.x;
    const int bh    = blockIdx.y;

    const float* Qbase = Q  + bh*SEQ*HEAD_DIM + qtile*BQ*HEAD_DIM;
    const float* Kbase = Kg + bh*SEQ*HEAD_DIM;
    const float* Vbase = Vg + bh*SEQ*HEAD_DIM;

#pragma unroll
    for (int it = 0; it < 8; ++it) {
        int idx = tid + it*256;
        int row = idx >> 4;
        int c4  = idx & 15;
        float4 v4 = *(const float4*)(Qbase + row*64 + c4*4);
        Qt[(c4*4+0)*QT_LD + row] = v4.x * 0.125f;
        Qt[(c4*4+1)*QT_LD + row] = v4.y * 0.125f;
        Qt[(c4*4+2)*QT_LD + row] = v4.z * 0.125f;
        Qt[(c4*4+3)*QT_LD + row] = v4.w * 0.125f;
    }

    float m_i[8], l_i[8], O[8][4];
#pragma unroll
    for (int i = 0; i < 8; ++i) {
        m_i[i] = -1e30f; l_i[i] = 0.f;
#pragma unroll
        for (int j = 0; j < 4; ++j) O[i][j] = 0.f;
    }

    for (int kt = 0; kt < SEQ/BK; ++kt) {
        __syncthreads();
        const float* Kp = Kbase + kt*BK*HEAD_DIM;
        const float* Vp = Vbase + kt*BK*HEAD_DIM;
#pragma unroll
        for (int it = 0; it < 4; ++it) {
            int idx = tid + it*256;
            int row = idx >> 4;
            int c4  = idx & 15;
            float4 kv = *(const float4*)(Kp + row*64 + c4*4);
            Kt[(c4*4+0)*KT_LD + row] = kv.x;
            Kt[(c4*4+1)*KT_LD + row] = kv.y;
            Kt[(c4*4+2)*KT_LD + row] = kv.z;
            Kt[(c4*4+3)*KT_LD + row] = kv.w;
            float4 vv = *(const float4*)(Vp + row*64 + c4*4);
            *(float4*)(Vs + row*64 + c4*4) = vv;
        }
        __syncthreads();

        float s[8][4];
#pragma unroll
        for (int i = 0; i < 8; ++i)
#pragma unroll
            for (int j = 0; j < 4; ++j) s[i][j] = 0.f;

#pragma unroll 8
        for (int d = 0; d < 64; ++d) {
            float qf[8], kf[4];
            *(float4*)&qf[0] = *(const float4*)&Qt[d*QT_LD + ty*8];
            *(float4*)&qf[4] = *(const float4*)&Qt[d*QT_LD + ty*8 + 4];
            *(float4*)&kf[0] = *(const float4*)&Kt[d*KT_LD + tx*4];
#pragma unroll
            for (int i = 0; i < 8; ++i)
#pragma unroll
                for (int j = 0; j < 4; ++j)
                    s[i][j] += qf[i] * kf[j];
        }

#pragma unroll
        for (int i = 0; i < 8; ++i) {
            float mx = fmaxf(fmaxf(s[i][0], s[i][1]), fmaxf(s[i][2], s[i][3]));
#pragma unroll
            for (int off = 8; off >= 1; off >>= 1)
                mx = fmaxf(mx, __shfl_xor_sync(0xffffffffu, mx, off));
            float m_new = fmaxf(m_i[i], mx);
            float alpha = __expf(m_i[i] - m_new);
            float sum = 0.f;
#pragma unroll
            for (int j = 0; j < 4; ++j) {
                float p = __expf(s[i][j] - m_new);
                s[i][j] = p;
                sum += p;
            }
#pragma unroll
            for (int off = 8; off >= 1; off >>= 1)
                sum += __shfl_xor_sync(0xffffffffu, sum, off);
            l_i[i] = l_i[i]*alpha + sum;
            m_i[i] = m_new;
#pragma unroll
            for (int j = 0; j < 4; ++j) O[i][j] *= alpha;
#pragma unroll
            for (int j = 0; j < 4; ++j)
                Pt[(tx*4+j)*PT_LD + ty*8 + i] = s[i][j];
        }
        __syncthreads();

#pragma unroll 8
        for (int k = 0; k < 64; ++k) {
            float pf[8], vf[4];
            *(float4*)&pf[0] = *(const float4*)&Pt[k*PT_LD + ty*8];
            *(float4*)&pf[4] = *(const float4*)&Pt[k*PT_LD + ty*8 + 4];
            *(float4*)&vf[0] = *(const float4*)&Vs[k*64 + tx*4];
#pragma unroll
            for (int i = 0; i < 8; ++i)
#pragma unroll
                for (int j = 0; j < 4; ++j)
                    O[i][j] += pf[i] * vf[j];
        }
    }

    int b = bh >> 4, h = bh & 15;
#pragma unroll
    for (int i = 0; i < 8; ++i) {
        int q = qtile*BQ + ty*8 + i;
        float inv = 1.f / l_i[i];
        float4 o4;
        o4.x = O[i][0]*inv; o4.y = O[i][1]*inv;
        o4.z = O[i][2]*inv; o4.w = O[i][3]*inv;
        *(float4*)(ctx + ((b << 11) + q)*1024 + h*64 + tx*4) = o4;
    }
}

// =============================================================================
extern "C" void kernel_launch(void* const* d_in, const int* in_sizes, int n_in,
                              void* d_out, int out_size)
{
    (void)in_sizes; (void)n_in; (void)out_size;
    const float* x  = (const float*)d_in[0];
    const float* Wq = (const float*)d_in[1];
    const float* bq = (const float*)d_in[2];
    const float* Wk = (const float*)d_in[3];
    const float* bk = (const float*)d_in[4];
    const float* Wv = (const float*)d_in[5];
    const float* bv = (const float*)d_in[6];
    const float* Wo = (const float*)d_in[7];
    const float* bo = (const float*)d_in[8];
    float* out = (float*)d_out;

    float *Qp, *Kp, *Vp, *Cp;
    __nv_bfloat16 *ahi, *alo, *whi, *wlo;
    cudaGetSymbolAddress((void**)&Qp,  g_Q);
    cudaGetSymbolAddress((void**)&Kp,  g_K);
    cudaGetSymbolAddress((void**)&Vp,  g_V);
    cudaGetSymbolAddress((void**)&Cp,  g_ctx);
    cudaGetSymbolAddress((void**)&ahi, g_ahi);
    cudaGetSymbolAddress((void**)&alo, g_alo);
    cudaGetSymbolAddress((void**)&whi, g_whi);
    cudaGetSymbolAddress((void**)&wlo, g_wlo);

    cudaFuncSetAttribute(attn_kernel,  cudaFuncAttributeMaxDynamicSharedMemorySize, ATTN_SMEM_BYTES);
    cudaFuncSetAttribute(gemm_qkv_mma, cudaFuncAttributeMaxDynamicSharedMemorySize, GEMM_SMEM);
    cudaFuncSetAttribute(gemm_out_mma, cudaFuncAttributeMaxDynamicSharedMemorySize, GEMM_SMEM);

    const int n4x = M_TOTAL*D_MODEL/4;
    const int n4w = D_MODEL*D_MODEL/4;

    split_kernel<<<(n4x+255)/256, 256>>>(x, ahi, alo, n4x);
    split_kernel<<<(n4w+255)/256, 256>>>(Wq, whi + 0*(size_t)D_MODEL*D_MODEL, wlo + 0*(size_t)D_MODEL*D_MODEL, n4w);
    split_kernel<<<(n4w+255)/256, 256>>>(Wk, whi + 1*(size_t)D_MODEL*D_MODEL, wlo + 1*(size_t)D_MODEL*D_MODEL, n4w);
    split_kernel<<<(n4w+255)/256, 256>>>(Wv, whi + 2*(size_t)D_MODEL*D_MODEL, wlo + 2*(size_t)D_MODEL*D_MODEL, n4w);
    split_kernel<<<(n4w+255)/256, 256>>>(Wo, whi + 3*(size_t)D_MODEL*D_MODEL, wlo + 3*(size_t)D_MODEL*D_MODEL, n4w);

    gemm_qkv_mma<<<dim3(8, 64, 3), 256, GEMM_SMEM>>>(
        ahi, alo, whi, wlo, bq, bk, bv, Qp, Kp, Vp);

    attn_kernel<<<dim3(SEQ/BQ, NB*NUM_HEADS), 256, ATTN_SMEM_BYTES>>>(Qp, Kp, Vp, Cp);

    split_kernel<<<(n4x+255)/256, 256>>>(Cp, ahi, alo, n4x);

    gemm_out_mma<<<dim3(8, 64, 1), 256, GEMM_SMEM>>>(ahi, alo, whi, wlo, bo, out);
}

// round 4
// speedup vs baseline: 2.6040x; 2.1385x over previous
#include <cuda_runtime.h>
#include <cuda_fp16.h>
#include <cuda_bf16.h>
#include <math.h>
#include <stdint.h>

#define D_MODEL 1024
#define NUM_HEADS 16
#define HEAD_DIM 64
#define NB 4
#define SEQ 2048
#define M_TOTAL (NB*SEQ)   // 8192

// ---------------- scratch (device globals: no allocation allowed) -------------
__device__ __half g_Qh[NB*NUM_HEADS*SEQ*HEAD_DIM];   // [B,H,S,Hd] fp16 (pre-scaled)
__device__ __half g_Kh[NB*NUM_HEADS*SEQ*HEAD_DIM];
__device__ __half g_Vh[NB*NUM_HEADS*SEQ*HEAD_DIM];
__device__ float  g_ctx[M_TOTAL*D_MODEL];            // [B,S,D]
__device__ __nv_bfloat16 g_ahi[M_TOTAL*D_MODEL];
__device__ __nv_bfloat16 g_alo[M_TOTAL*D_MODEL];
__device__ __nv_bfloat16 g_whi[4*D_MODEL*D_MODEL];
__device__ __nv_bfloat16 g_wlo[4*D_MODEL*D_MODEL];

// =============================== PTX helpers =================================
__device__ __forceinline__ uint32_t smem_u32(const void* p) {
    uint32_t a;
    asm("{ .reg .u64 t; cvta.to.shared.u64 t, %1; cvt.u32.u64 %0, t; }" : "=r"(a) : "l"(p));
    return a;
}

#define CP16(dst, src) \
    asm volatile("cp.async.cg.shared.global [%0], [%1], 16;" :: "r"(dst), "l"(src))
#define CP_COMMIT() asm volatile("cp.async.commit_group;" ::: "memory")
#define CP_WAIT(N)  asm volatile("cp.async.wait_group %0;" :: "n"(N) : "memory")

#define LDSM4(r, addr) \
    asm volatile("ldmatrix.sync.aligned.m8n8.x4.shared.b16 {%0,%1,%2,%3}, [%4];" \
        : "=r"((r)[0]), "=r"((r)[1]), "=r"((r)[2]), "=r"((r)[3]) : "r"(addr))

#define LDSM4T(r, addr) \
    asm volatile("ldmatrix.sync.aligned.m8n8.x4.trans.shared.b16 {%0,%1,%2,%3}, [%4];" \
        : "=r"((r)[0]), "=r"((r)[1]), "=r"((r)[2]), "=r"((r)[3]) : "r"(addr))

#define MMA_BF16(c, a, b) \
    asm volatile("mma.sync.aligned.m16n8k16.row.col.f32.bf16.bf16.f32 " \
        "{%0,%1,%2,%3}, {%4,%5,%6,%7}, {%8,%9}, {%0,%1,%2,%3};" \
        : "+f"((c)[0]), "+f"((c)[1]), "+f"((c)[2]), "+f"((c)[3]) \
        : "r"((a)[0]), "r"((a)[1]), "r"((a)[2]), "r"((a)[3]), \
          "r"((b)[0]), "r"((b)[1]))

#define MMA_FP16(c, a, b) \
    asm volatile("mma.sync.aligned.m16n8k16.row.col.f32.f16.f16.f32 " \
        "{%0,%1,%2,%3}, {%4,%5,%6,%7}, {%8,%9}, {%0,%1,%2,%3};" \
        : "+f"((c)[0]), "+f"((c)[1]), "+f"((c)[2]), "+f"((c)[3]) \
        : "r"((a)[0]), "r"((a)[1]), "r"((a)[2]), "r"((a)[3]), \
          "r"((b)[0]), "r"((b)[1]))

// =============================================================================
// bf16-split mma.sync GEMM (from R3): C = (Ah+Al) @ (Wh+Wl)^T + bias
// mode 0: fp16 scatter into [B,H,S,Hd] with per-output scale; mode 1: fp32 rm.
// =============================================================================
#define TSTR   40
#define TILE_B (128*TSTR*2)
#define STAGE_B (4*TILE_B)
#define GSTAGES 3
#define GEMM_SMEM (GSTAGES*STAGE_B)

__device__ __forceinline__ void gemm_mma_body(
    const __nv_bfloat16* __restrict__ Ah, const __nv_bfloat16* __restrict__ Al,
    const __nv_bfloat16* __restrict__ Wh, const __nv_bfloat16* __restrict__ Wl,
    const float* __restrict__ bias, void* __restrict__ Cv, int mode, float oscale)
{
    extern __shared__ char smraw[];
    const uint32_t smb = smem_u32(smraw);
    const int tid  = threadIdx.x;
    const int lane = tid & 31;
    const int wid  = tid >> 5;
    const int wm   = wid & 1;
    const int wn   = wid >> 1;
    const int bm   = blockIdx.y * 128;
    const int bn   = blockIdx.x * 128;

    const int lrow = tid >> 1;
    const int lcol = (tid & 1) * 2;

    const __nv_bfloat16* gA0 = Ah + (size_t)(bm + lrow) * 1024 + lcol * 8;
    const __nv_bfloat16* gA1 = Al + (size_t)(bm + lrow) * 1024 + lcol * 8;
    const __nv_bfloat16* gW0 = Wh + (size_t)(bn + lrow) * 1024 + lcol * 8;
    const __nv_bfloat16* gW1 = Wl + (size_t)(bn + lrow) * 1024 + lcol * 8;
    const uint32_t dstb = smb + lrow * 80 + lcol * 16;

#define LOAD_STAGE(kt) do { \
        const int _st = (kt) % GSTAGES; \
        const uint32_t _d = dstb + _st * STAGE_B; \
        const int _k0 = (kt) * 32; \
        CP16(_d,                gA0 + _k0); CP16(_d + 16,              gA0 + _k0 + 8); \
        CP16(_d +   TILE_B,     gA1 + _k0); CP16(_d +   TILE_B + 16,   gA1 + _k0 + 8); \
        CP16(_d + 2*TILE_B,     gW0 + _k0); CP16(_d + 2*TILE_B + 16,   gW0 + _k0 + 8); \
        CP16(_d + 3*TILE_B,     gW1 + _k0); CP16(_d + 3*TILE_B + 16,   gW1 + _k0 + 8); \
        CP_COMMIT(); \
    } while (0)

    LOAD_STAGE(0);
    LOAD_STAGE(1);

    float acc[4][4][4];
#pragma unroll
    for (int i = 0; i < 4; ++i)
#pragma unroll
        for (int j = 0; j < 4; ++j)
#pragma unroll
            for (int r = 0; r < 4; ++r) acc[i][j][r] = 0.f;

    const uint32_t a_base = smb + ((wm*64 + (lane & 15)) * TSTR + (lane >> 4) * 8) * 2;
    const uint32_t b_base = smb + ((wn*32 + (lane & 15)) * TSTR + (lane >> 4) * 8) * 2;

    for (int kt = 0; kt < 32; ++kt) {
        if (kt < 30) { CP_WAIT(1); } else { CP_WAIT(0); }
        __syncthreads();
        if (kt + 2 < 32) LOAD_STAGE(kt + 2);

        const uint32_t stoff = (uint32_t)(kt % GSTAGES) * STAGE_B;
#pragma unroll
        for (int kk = 0; kk < 2; ++kk) {
            const uint32_t ko = stoff + kk * 32;
            uint32_t ah[4][4], al[4][4], wh2[2][4], wl2[2][4];
#pragma unroll
            for (int i = 0; i < 4; ++i) {
                LDSM4(ah[i], a_base + ko + i*16*80);
                LDSM4(al[i], a_base + ko + TILE_B + i*16*80);
            }
#pragma unroll
            for (int j = 0; j < 2; ++j) {
                LDSM4(wh2[j], b_base + ko + 2*TILE_B + j*16*80);
                LDSM4(wl2[j], b_base + ko + 3*TILE_B + j*16*80);
            }
#pragma unroll
            for (int mi = 0; mi < 4; ++mi)
#pragma unroll
                for (int nj = 0; nj < 4; ++nj) {
                    uint32_t bh[2] = { wh2[nj>>1][nj&1], wh2[nj>>1][(nj&1)+2] };
                    uint32_t bl[2] = { wl2[nj>>1][nj&1], wl2[nj>>1][(nj&1)+2] };
                    MMA_BF16(acc[mi][nj], ah[mi], bh);
                    MMA_BF16(acc[mi][nj], ah[mi], bl);
                    MMA_BF16(acc[mi][nj], al[mi], bh);
                }
        }
    }

#pragma unroll
    for (int mi = 0; mi < 4; ++mi) {
#pragma unroll
        for (int nj = 0; nj < 4; ++nj) {
            const int m0 = bm + wm*64 + mi*16 + (lane >> 2);
            const int n0 = bn + wn*32 + nj*8 + (lane & 3)*2;
            float2 bb = *(const float2*)(bias + n0);
            float2 v0, v1;
            v0.x = acc[mi][nj][0] + bb.x;  v0.y = acc[mi][nj][1] + bb.y;
            v1.x = acc[mi][nj][2] + bb.x;  v1.y = acc[mi][nj][3] + bb.y;
            if (mode == 0) {
                __half* Ch = (__half*)Cv;
                const int h = n0 >> 6, hd = n0 & 63;
                const int b0_ = m0 >> 11, s0 = m0 & 2047;
                const int b1_ = (m0+8) >> 11, s1 = (m0+8) & 2047;
                __half2 h0 = __floats2half2_rn(v0.x*oscale, v0.y*oscale);
                __half2 h1 = __floats2half2_rn(v1.x*oscale, v1.y*oscale);
                *(__half2*)(Ch + ((((size_t)(b0_*NUM_HEADS + h) << 11) + s0) << 6) + hd) = h0;
                *(__half2*)(Ch + ((((size_t)(b1_*NUM_HEADS + h) << 11) + s1) << 6) + hd) = h1;
            } else {
                float* C = (float*)Cv;
                *(float2*)(C + (size_t)m0*1024 + n0) = v0;
                *(float2*)(C + (size_t)(m0+8)*1024 + n0) = v1;
            }
        }
    }
#undef LOAD_STAGE
}

__global__ void __launch_bounds__(256, 1)
gemm_qkv_mma(const __nv_bfloat16* ah, const __nv_bfloat16* al,
             const __nv_bfloat16* wh, const __nv_bfloat16* wl,
             const float* b0, const float* b1, const float* b2,
             __half* C0, __half* C1, __half* C2)
{
    const int z = blockIdx.z;
    const __nv_bfloat16* whz = wh + (size_t)z * D_MODEL * D_MODEL;
    const __nv_bfloat16* wlz = wl + (size_t)z * D_MODEL * D_MODEL;
    const float* bias = (z == 0) ? b0 : (z == 1) ? b1 : b2;
    __half* C = (z == 0) ? C0 : (z == 1) ? C1 : C2;
    gemm_mma_body(ah, al, whz, wlz, bias, C, 0, (z == 0) ? 0.125f : 1.0f);
}

__global__ void __launch_bounds__(256, 1)
gemm_out_mma(const __nv_bfloat16* ah, const __nv_bfloat16* al,
             const __nv_bfloat16* wh, const __nv_bfloat16* wl,
             const float* bias, float* C)
{
    gemm_mma_body(ah, al, wh + (size_t)3*D_MODEL*D_MODEL,
                  wl + (size_t)3*D_MODEL*D_MODEL, bias, C, 1, 1.0f);
}

// ======================= fp32 -> bf16 hi/lo split =============================
__global__ void __launch_bounds__(256)
split_kernel(const float* __restrict__ in, __nv_bfloat16* __restrict__ hi,
             __nv_bfloat16* __restrict__ lo, int n4)
{
    int i = blockIdx.x * 256 + threadIdx.x;
    if (i >= n4) return;
    float4 v = ((const float4*)in)[i];
    __nv_bfloat16 hx = __float2bfloat16_rn(v.x);
    __nv_bfloat16 hy = __float2bfloat16_rn(v.y);
    __nv_bfloat16 hz = __float2bfloat16_rn(v.z);
    __nv_bfloat16 hw = __float2bfloat16_rn(v.w);
    float lx = v.x - __bfloat162float(hx);
    float ly = v.y - __bfloat162float(hy);
    float lz = v.z - __bfloat162float(hz);
    float lw = v.w - __bfloat162float(hw);
    __nv_bfloat162* hp = (__nv_bfloat162*)hi;
    __nv_bfloat162* lp = (__nv_bfloat162*)lo;
    hp[2*i+0] = __nv_bfloat162(hx, hy);
    hp[2*i+1] = __nv_bfloat162(hz, hw);
    lp[2*i+0] = __floats2bfloat162_rn(lx, ly);
    lp[2*i+1] = __floats2bfloat162_rn(lz, lw);
}

// =============================================================================
// Tensor-core flash attention (fp16 mma.sync, P hi/lo split on PV).
// CTA: 128 q-rows of one (b,h); 8 warps x 16 rows; 32 key-tiles of 64,
// cp.async double-buffered. ctx out fp32 [B,S,D].
// =============================================================================
#define AT_STRB 144                      // smem row stride bytes (72 halves)
#define Q_SMB  (128*AT_STRB)             // 18432
#define KV_SMB (64*AT_STRB)              // 9216
#define ATTN_SMEM2 (Q_SMB + 4*KV_SMB)    // 55296

__global__ void __launch_bounds__(256, 2)
attn_mma_kernel(const __half* __restrict__ Qg, const __half* __restrict__ Kg,
                const __half* __restrict__ Vg, float* __restrict__ ctx)
{
    extern __shared__ char smraw[];
    const uint32_t sQ  = smem_u32(smraw);
    const uint32_t sKV = sQ + Q_SMB;     // stage s: K at sKV + s*2*KV_SMB, V at +KV_SMB
    const int tid  = threadIdx.x;
    const int lane = tid & 31;
    const int wid  = tid >> 5;
    const int qtile = blockIdx.x;
    const int bh    = blockIdx.y;

    const char* Qbase = (const char*)(Qg + (size_t)bh*SEQ*64 + (size_t)qtile*128*64);
    const char* Kbase = (const char*)(Kg + (size_t)bh*SEQ*64);
    const char* Vbase = (const char*)(Vg + (size_t)bh*SEQ*64);

    // prologue: Q tile + K/V tile 0 (one cp.async group)
#pragma unroll
    for (int it = 0; it < 4; ++it) {
        int idx = tid + it*256;          // 0..1023
        int row = idx >> 3, ch = idx & 7;
        CP16(sQ + row*AT_STRB + ch*16, Qbase + row*128 + ch*16);
    }
#pragma unroll
    for (int it = 0; it < 2; ++it) {
        int idx = tid + it*256;          // 0..511
        int row = idx >> 3, ch = idx & 7;
        CP16(sKV + row*AT_STRB + ch*16,            Kbase + row*128 + ch*16);
        CP16(sKV + KV_SMB + row*AT_STRB + ch*16,   Vbase + row*128 + ch*16);
    }
    CP_COMMIT();

    float m0 = -1e30f, m1 = -1e30f, l0 = 0.f, l1 = 0.f;
    float O[8][4];
#pragma unroll
    for (int j = 0; j < 8; ++j)
#pragma unroll
        for (int r = 0; r < 4; ++r) O[j][r] = 0.f;

    uint32_t qf[4][4];                   // Q A-frags, loaded once

    for (int kt = 0; kt < SEQ/64; ++kt) {
        if (kt + 1 < SEQ/64) {
            const uint32_t dst = sKV + ((kt+1)&1)*(2*KV_SMB);
            const char* Ks = Kbase + (size_t)(kt+1)*64*128;
            const char* Vs = Vbase + (size_t)(kt+1)*64*128;
#pragma unroll
            for (int it = 0; it < 2; ++it) {
                int idx = tid + it*256;
                int row = idx >> 3, ch = idx & 7;
                CP16(dst + row*AT_STRB + ch*16,          Ks + row*128 + ch*16);
                CP16(dst + KV_SMB + row*AT_STRB + ch*16, Vs + row*128 + ch*16);
            }
            CP_COMMIT();
            CP_WAIT(1);
        } else {
            CP_WAIT(0);
        }
        __syncthreads();

        if (kt == 0) {
            const uint32_t qb = sQ + (wid*16 + (lane & 15))*AT_STRB + (lane >> 4)*16;
#pragma unroll
            for (int kk = 0; kk < 4; ++kk)
                LDSM4(qf[kk], qb + kk*32);
        }

        const uint32_t sK = sKV + (kt&1)*(2*KV_SMB);
        const uint32_t sV = sK + KV_SMB;

        // ---- S = Q @ K^T ----
        float c[8][4];
#pragma unroll
        for (int j = 0; j < 8; ++j)
#pragma unroll
            for (int r = 0; r < 4; ++r) c[j][r] = 0.f;

#pragma unroll
        for (int kk = 0; kk < 4; ++kk) {
            const uint32_t kb = sK + (lane & 15)*AT_STRB + (lane >> 4)*16 + kk*32;
#pragma unroll
            for (int j4 = 0; j4 < 4; ++j4) {
                uint32_t b[4];
                LDSM4(b, kb + j4*16*AT_STRB);
                uint32_t bj0[2] = { b[0], b[2] };
                uint32_t bj1[2] = { b[1], b[3] };
                MMA_FP16(c[2*j4],   qf[kk], bj0);
                MMA_FP16(c[2*j4+1], qf[kk], bj1);
            }
        }

        // ---- online softmax (rows r = lane>>2 and r+8; quad-local reductions)
        float mx0 = c[0][0], mx1 = c[0][2];
#pragma unroll
        for (int j = 0; j < 8; ++j) {
            mx0 = fmaxf(mx0, fmaxf(c[j][0], c[j][1]));
            mx1 = fmaxf(mx1, fmaxf(c[j][2], c[j][3]));
        }
        mx0 = fmaxf(mx0, __shfl_xor_sync(0xffffffffu, mx0, 1));
        mx0 = fmaxf(mx0, __shfl_xor_sync(0xffffffffu, mx0, 2));
        mx1 = fmaxf(mx1, __shfl_xor_sync(0xffffffffu, mx1, 1));
        mx1 = fmaxf(mx1, __shfl_xor_sync(0xffffffffu, mx1, 2));
        const float mn0 = fmaxf(m0, mx0), mn1 = fmaxf(m1, mx1);
        const float a0 = __expf(m0 - mn0), a1 = __expf(m1 - mn1);
        m0 = mn0; m1 = mn1;

        float s0 = 0.f, s1 = 0.f;
        uint32_t ph[8][2], pl[8][2];
#pragma unroll
        for (int j = 0; j < 8; ++j) {
            float p0 = __expf(c[j][0] - m0);
            float p1 = __expf(c[j][1] - m0);
            float p2 = __expf(c[j][2] - m1);
            float p3 = __expf(c[j][3] - m1);
            s0 += p0 + p1;  s1 += p2 + p3;
            __half2 h01 = __floats2half2_rn(p0, p1);
            __half2 h23 = __floats2half2_rn(p2, p3);
            ph[j][0] = *(uint32_t*)&h01;
            ph[j][1] = *(uint32_t*)&h23;
            float2 f01 = __half22float2(h01);
            float2 f23 = __half22float2(h23);
            __half2 e01 = __floats2half2_rn(p0 - f01.x, p1 - f01.y);
            __half2 e23 = __floats2half2_rn(p2 - f23.x, p3 - f23.y);
            pl[j][0] = *(uint32_t*)&e01;
            pl[j][1] = *(uint32_t*)&e23;
        }
        s0 += __shfl_xor_sync(0xffffffffu, s0, 1);
        s0 += __shfl_xor_sync(0xffffffffu, s0, 2);
        s1 += __shfl_xor_sync(0xffffffffu, s1, 1);
        s1 += __shfl_xor_sync(0xffffffffu, s1, 2);
        l0 = l0*a0 + s0;
        l1 = l1*a1 + s1;
#pragma unroll
        for (int j = 0; j < 8; ++j) {
            O[j][0] *= a0; O[j][1] *= a0;
            O[j][2] *= a1; O[j][3] *= a1;
        }

        // ---- O += (Ph + Pl) @ V ----
#pragma unroll
        for (int kk = 0; kk < 4; ++kk) {
            uint32_t aPh[4] = { ph[2*kk][0], ph[2*kk][1], ph[2*kk+1][0], ph[2*kk+1][1] };
            uint32_t aPl[4] = { pl[2*kk][0], pl[2*kk][1], pl[2*kk+1][0], pl[2*kk+1][1] };
            const uint32_t vb = sV + (16*kk + (lane & 15))*AT_STRB + (lane >> 4)*16;
#pragma unroll
            for (int dn4 = 0; dn4 < 4; ++dn4) {
                uint32_t b[4];
                LDSM4T(b, vb + dn4*32);
                uint32_t b0[2] = { b[0], b[1] };
                uint32_t b1[2] = { b[2], b[3] };
                MMA_FP16(O[2*dn4],   aPh, b0);
                MMA_FP16(O[2*dn4],   aPl, b0);
                MMA_FP16(O[2*dn4+1], aPh, b1);
                MMA_FP16(O[2*dn4+1], aPl, b1);
            }
        }
        __syncthreads();
    }

    // ---- epilogue: ctx[b][q][h*64 + d] = O / l ----
    const int b = bh >> 4, h = bh & 15;
    const int q0 = qtile*128 + wid*16 + (lane >> 2);
    const float inv0 = 1.f / l0, inv1 = 1.f / l1;
#pragma unroll
    for (int j = 0; j < 8; ++j) {
        const int col = h*64 + j*8 + (lane & 3)*2;
        float2 v0, v1;
        v0.x = O[j][0]*inv0;  v0.y = O[j][1]*inv0;
        v1.x = O[j][2]*inv1;  v1.y = O[j][3]*inv1;
        *(float2*)(ctx + ((size_t)(b*SEQ + q0)    )*1024 + col) = v0;
        *(float2*)(ctx + ((size_t)(b*SEQ + q0 + 8))*1024 + col) = v1;
    }
}

// =============================================================================
extern "C" void kernel_launch(void* const* d_in, const int* in_sizes, int n_in,
                              void* d_out, int out_size)
{
    (void)in_sizes; (void)n_in; (void)out_size;
    const float* x  = (const float*)d_in[0];
    const float* Wq = (const float*)d_in[1];
    const float* bq = (const float*)d_in[2];
    const float* Wk = (const float*)d_in[3];
    const float* bk = (const float*)d_in[4];
    const float* Wv = (const float*)d_in[5];
    const float* bv = (const float*)d_in[6];
    const float* Wo = (const float*)d_in[7];
    const float* bo = (const float*)d_in[8];
    float* out = (float*)d_out;

    __half *Qp, *Kp, *Vp;
    float *Cp;
    __nv_bfloat16 *ahi, *alo, *whi, *wlo;
    cudaGetSymbolAddress((void**)&Qp,  g_Qh);
    cudaGetSymbolAddress((void**)&Kp,  g_Kh);
    cudaGetSymbolAddress((void**)&Vp,  g_Vh);
    cudaGetSymbolAddress((void**)&Cp,  g_ctx);
    cudaGetSymbolAddress((void**)&ahi, g_ahi);
    cudaGetSymbolAddress((void**)&alo, g_alo);
    cudaGetSymbolAddress((void**)&whi, g_whi);
    cudaGetSymbolAddress((void**)&wlo, g_wlo);

    cudaFuncSetAttribute(attn_mma_kernel, cudaFuncAttributeMaxDynamicSharedMemorySize, ATTN_SMEM2);
    cudaFuncSetAttribute(gemm_qkv_mma, cudaFuncAttributeMaxDynamicSharedMemorySize, GEMM_SMEM);
    cudaFuncSetAttribute(gemm_out_mma, cudaFuncAttributeMaxDynamicSharedMemorySize, GEMM_SMEM);

    const int n4x = M_TOTAL*D_MODEL/4;
    const int n4w = D_MODEL*D_MODEL/4;

    split_kernel<<<(n4x+255)/256, 256>>>(x, ahi, alo, n4x);
    split_kernel<<<(n4w+255)/256, 256>>>(Wq, whi + 0*(size_t)D_MODEL*D_MODEL, wlo + 0*(size_t)D_MODEL*D_MODEL, n4w);
    split_kernel<<<(n4w+255)/256, 256>>>(Wk, whi + 1*(size_t)D_MODEL*D_MODEL, wlo + 1*(size_t)D_MODEL*D_MODEL, n4w);
    split_kernel<<<(n4w+255)/256, 256>>>(Wv, whi + 2*(size_t)D_MODEL*D_MODEL, wlo + 2*(size_t)D_MODEL*D_MODEL, n4w);
    split_kernel<<<(n4w+255)/256, 256>>>(Wo, whi + 3*(size_t)D_MODEL*D_MODEL, wlo + 3*(size_t)D_MODEL*D_MODEL, n4w);

    gemm_qkv_mma<<<dim3(8, 64, 3), 256, GEMM_SMEM>>>(
        ahi, alo, whi, wlo, bq, bk, bv, Qp, Kp, Vp);

    attn_mma_kernel<<<dim3(SEQ/128, NB*NUM_HEADS), 256, ATTN_SMEM2>>>(Qp, Kp, Vp, Cp);

    split_kernel<<<(n4x+255)/256, 256>>>(Cp, ahi, alo, n4x);

    gemm_out_mma<<<dim3(8, 64, 1), 256, GEMM_SMEM>>>(ahi, alo, whi, wlo, bo, out);
}

// round 5
// speedup vs baseline: 3.4676x; 1.3316x over previous
#include <cuda_runtime.h>
#include <cuda_fp16.h>
#include <math.h>
#include <stdint.h>

#define D_MODEL 1024
#define NUM_HEADS 16
#define HEAD_DIM 64
#define NB 4
#define SEQ 2048
#define M_TOTAL (NB*SEQ)   // 8192

// ---------------- scratch (device globals: no allocation allowed) -------------
__device__ __half g_xh[M_TOTAL*D_MODEL];     // x hi (fp16)
__device__ __half g_xl[M_TOTAL*D_MODEL];     // x lo (fp16 residual)
__device__ __half g_wh[4*D_MODEL*D_MODEL];   // weights fp16 (q,k,v,o)
__device__ __half g_Qh[NB*NUM_HEADS*SEQ*HEAD_DIM];   // [B,H,S,Hd] pre-scaled
__device__ __half g_Kh[NB*NUM_HEADS*SEQ*HEAD_DIM];
__device__ __half g_Vh[NB*NUM_HEADS*SEQ*HEAD_DIM];
__device__ __half g_cthi[M_TOTAL*D_MODEL];   // ctx hi (fp16) [B,S,D]
__device__ __half g_ctlo[M_TOTAL*D_MODEL];   // ctx lo

// =============================== PTX helpers =================================
__device__ __forceinline__ uint32_t smem_u32(const void* p) {
    uint32_t a;
    asm("{ .reg .u64 t; cvta.to.shared.u64 t, %1; cvt.u32.u64 %0, t; }" : "=r"(a) : "l"(p));
    return a;
}

#define CP16(dst, src) \
    asm volatile("cp.async.cg.shared.global [%0], [%1], 16;" :: "r"(dst), "l"(src))
#define CP_COMMIT() asm volatile("cp.async.commit_group;" ::: "memory")
#define CP_WAIT(N)  asm volatile("cp.async.wait_group %0;" :: "n"(N) : "memory")

#define LDSM4(r, addr) \
    asm volatile("ldmatrix.sync.aligned.m8n8.x4.shared.b16 {%0,%1,%2,%3}, [%4];" \
        : "=r"((r)[0]), "=r"((r)[1]), "=r"((r)[2]), "=r"((r)[3]) : "r"(addr))

#define LDSM4T(r, addr) \
    asm volatile("ldmatrix.sync.aligned.m8n8.x4.trans.shared.b16 {%0,%1,%2,%3}, [%4];" \
        : "=r"((r)[0]), "=r"((r)[1]), "=r"((r)[2]), "=r"((r)[3]) : "r"(addr))

#define MMA_FP16(c, a, b) \
    asm volatile("mma.sync.aligned.m16n8k16.row.col.f32.f16.f16.f32 " \
        "{%0,%1,%2,%3}, {%4,%5,%6,%7}, {%8,%9}, {%0,%1,%2,%3};" \
        : "+f"((c)[0]), "+f"((c)[1]), "+f"((c)[2]), "+f"((c)[3]) \
        : "r"((a)[0]), "r"((a)[1]), "r"((a)[2]), "r"((a)[3]), \
          "r"((b)[0]), "r"((b)[1]))

// =============================================================================
// fp16 2-term mma.sync GEMM: C = (Ah+Al)[M,K] @ W[N,K]^T + bias
// BM=BN=128, BK=32, 4-stage cp.async, 8 warps of 64x32 warp tiles.
// smem tile stride 80B (conflict-free ldmatrix). 3 tiles/stage (Ah, Al, W).
// mode 0: fp16 scatter into [B,H,S,Hd] with scale; mode 1: fp32 row-major.
// =============================================================================
#define TSTR   40
#define TILE_B (128*TSTR*2)       // 10240 B
#define STAGE_B (3*TILE_B)        // 30720 B
#define GSTAGES 4
#define GEMM_SMEM (GSTAGES*STAGE_B)   // 122880 B

__device__ __forceinline__ void gemm_mma_body(
    const __half* __restrict__ Ah, const __half* __restrict__ Al,
    const __half* __restrict__ W,
    const float* __restrict__ bias, void* __restrict__ Cv, int mode, float oscale)
{
    extern __shared__ char smraw[];
    const uint32_t smb = smem_u32(smraw);
    const int tid  = threadIdx.x;
    const int lane = tid & 31;
    const int wid  = tid >> 5;
    const int wm   = wid & 1;
    const int wn   = wid >> 1;
    const int bm   = blockIdx.y * 128;
    const int bn   = blockIdx.x * 128;

    const int lrow = tid >> 1;
    const int lcol = (tid & 1) * 2;

    const __half* gA0 = Ah + (size_t)(bm + lrow) * 1024 + lcol * 8;
    const __half* gA1 = Al + (size_t)(bm + lrow) * 1024 + lcol * 8;
    const __half* gW0 = W  + (size_t)(bn + lrow) * 1024 + lcol * 8;
    const uint32_t dstb = smb + lrow * 80 + lcol * 16;

#define LOAD_STAGE(kt) do { \
        const int _st = (kt) % GSTAGES; \
        const uint32_t _d = dstb + _st * STAGE_B; \
        const int _k0 = (kt) * 32; \
        CP16(_d,                gA0 + _k0); CP16(_d + 16,              gA0 + _k0 + 8); \
        CP16(_d +   TILE_B,     gA1 + _k0); CP16(_d +   TILE_B + 16,   gA1 + _k0 + 8); \
        CP16(_d + 2*TILE_B,     gW0 + _k0); CP16(_d + 2*TILE_B + 16,   gW0 + _k0 + 8); \
        CP_COMMIT(); \
    } while (0)

    LOAD_STAGE(0);
    LOAD_STAGE(1);
    LOAD_STAGE(2);

    float acc[4][4][4];
#pragma unroll
    for (int i = 0; i < 4; ++i)
#pragma unroll
        for (int j = 0; j < 4; ++j)
#pragma unroll
            for (int r = 0; r < 4; ++r) acc[i][j][r] = 0.f;

    const uint32_t a_base = smb + ((wm*64 + (lane & 15)) * TSTR + (lane >> 4) * 8) * 2;
    const uint32_t b_base = smb + ((wn*32 + (lane & 15)) * TSTR + (lane >> 4) * 8) * 2;

    for (int kt = 0; kt < 32; ++kt) {
        if (kt < 29) { CP_WAIT(2); } else { CP_WAIT(0); }
        __syncthreads();
        if (kt + 3 < 32) LOAD_STAGE(kt + 3);

        const uint32_t stoff = (uint32_t)(kt % GSTAGES) * STAGE_B;
#pragma unroll
        for (int kk = 0; kk < 2; ++kk) {
            const uint32_t ko = stoff + kk * 32;
            uint32_t ah[4][4], al[4][4], wf[2][4];
#pragma unroll
            for (int i = 0; i < 4; ++i) {
                LDSM4(ah[i], a_base + ko + i*16*80);
                LDSM4(al[i], a_base + ko + TILE_B + i*16*80);
            }
#pragma unroll
            for (int j = 0; j < 2; ++j)
                LDSM4(wf[j], b_base + ko + 2*TILE_B + j*16*80);
#pragma unroll
            for (int mi = 0; mi < 4; ++mi)
#pragma unroll
                for (int nj = 0; nj < 4; ++nj) {
                    uint32_t bb[2] = { wf[nj>>1][nj&1], wf[nj>>1][(nj&1)+2] };
                    MMA_FP16(acc[mi][nj], ah[mi], bb);
                    MMA_FP16(acc[mi][nj], al[mi], bb);
                }
        }
    }

#pragma unroll
    for (int mi = 0; mi < 4; ++mi) {
#pragma unroll
        for (int nj = 0; nj < 4; ++nj) {
            const int m0 = bm + wm*64 + mi*16 + (lane >> 2);
            const int n0 = bn + wn*32 + nj*8 + (lane & 3)*2;
            float2 bb = *(const float2*)(bias + n0);
            float2 v0, v1;
            v0.x = acc[mi][nj][0] + bb.x;  v0.y = acc[mi][nj][1] + bb.y;
            v1.x = acc[mi][nj][2] + bb.x;  v1.y = acc[mi][nj][3] + bb.y;
            if (mode == 0) {
                __half* Ch = (__half*)Cv;
                const int h = n0 >> 6, hd = n0 & 63;
                const int b0_ = m0 >> 11, s0 = m0 & 2047;
                const int b1_ = (m0+8) >> 11, s1 = (m0+8) & 2047;
                __half2 h0 = __floats2half2_rn(v0.x*oscale, v0.y*oscale);
                __half2 h1 = __floats2half2_rn(v1.x*oscale, v1.y*oscale);
                *(__half2*)(Ch + ((((size_t)(b0_*NUM_HEADS + h) << 11) + s0) << 6) + hd) = h0;
                *(__half2*)(Ch + ((((size_t)(b1_*NUM_HEADS + h) << 11) + s1) << 6) + hd) = h1;
            } else {
                float* C = (float*)Cv;
                *(float2*)(C + (size_t)m0*1024 + n0) = v0;
                *(float2*)(C + (size_t)(m0+8)*1024 + n0) = v1;
            }
        }
    }
#undef LOAD_STAGE
}

__global__ void __launch_bounds__(256, 1)
gemm_qkv_mma(const __half* ah, const __half* al, const __half* wh,
             const float* b0, const float* b1, const float* b2,
             __half* C0, __half* C1, __half* C2)
{
    const int z = blockIdx.z;
    const __half* wz = wh + (size_t)z * D_MODEL * D_MODEL;
    const float* bias = (z == 0) ? b0 : (z == 1) ? b1 : b2;
    __half* C = (z == 0) ? C0 : (z == 1) ? C1 : C2;
    gemm_mma_body(ah, al, wz, bias, C, 0, (z == 0) ? 0.125f : 1.0f);
}

__global__ void __launch_bounds__(256, 1)
gemm_out_mma(const __half* ah, const __half* al, const __half* wh,
             const float* bias, float* C)
{
    gemm_mma_body(ah, al, wh + (size_t)3*D_MODEL*D_MODEL, bias, C, 1, 1.0f);
}

// ================== fp32 -> fp16 hi/lo split, and fp16 convert =================
__global__ void __launch_bounds__(256)
split_kernel(const float* __restrict__ in, __half* __restrict__ hi,
             __half* __restrict__ lo, int n4)
{
    int i = blockIdx.x * 256 + threadIdx.x;
    if (i >= n4) return;
    float4 v = ((const float4*)in)[i];
    __half2 h0 = __floats2half2_rn(v.x, v.y);
    __half2 h1 = __floats2half2_rn(v.z, v.w);
    float2 f0 = __half22float2(h0);
    float2 f1 = __half22float2(h1);
    __half2 l0 = __floats2half2_rn(v.x - f0.x, v.y - f0.y);
    __half2 l1 = __floats2half2_rn(v.z - f1.x, v.w - f1.y);
    __half2* hp = (__half2*)hi;
    __half2* lp = (__half2*)lo;
    hp[2*i+0] = h0;  hp[2*i+1] = h1;
    lp[2*i+0] = l0;  lp[2*i+1] = l1;
}

__global__ void __launch_bounds__(256)
conv_kernel(const float* __restrict__ in, __half* __restrict__ out, int n4)
{
    int i = blockIdx.x * 256 + threadIdx.x;
    if (i >= n4) return;
    float4 v = ((const float4*)in)[i];
    __half2* op = (__half2*)out;
    op[2*i+0] = __floats2half2_rn(v.x, v.y);
    op[2*i+1] = __floats2half2_rn(v.z, v.w);
}

// =============================================================================
// Tensor-core flash attention (fp16 mma.sync). Epilogue writes ctx hi/lo fp16.
// CTA: 128 q-rows of one (b,h); 8 warps x 16 rows; 32 key-tiles of 64,
// cp.async double-buffered.
// =============================================================================
#define AT_STRB 144
#define Q_SMB  (128*AT_STRB)
#define KV_SMB (64*AT_STRB)
#define ATTN_SMEM2 (Q_SMB + 4*KV_SMB)

__global__ void __launch_bounds__(256, 2)
attn_mma_kernel(const __half* __restrict__ Qg, const __half* __restrict__ Kg,
                const __half* __restrict__ Vg,
                __half* __restrict__ cthi, __half* __restrict__ ctlo)
{
    extern __shared__ char smraw[];
    const uint32_t sQ  = smem_u32(smraw);
    const uint32_t sKV = sQ + Q_SMB;
    const int tid  = threadIdx.x;
    const int lane = tid & 31;
    const int wid  = tid >> 5;
    const int qtile = blockIdx.x;
    const int bh    = blockIdx.y;

    const char* Qbase = (const char*)(Qg + (size_t)bh*SEQ*64 + (size_t)qtile*128*64);
    const char* Kbase = (const char*)(Kg + (size_t)bh*SEQ*64);
    const char* Vbase = (const char*)(Vg + (size_t)bh*SEQ*64);

#pragma unroll
    for (int it = 0; it < 4; ++it) {
        int idx = tid + it*256;
        int row = idx >> 3, ch = idx & 7;
        CP16(sQ + row*AT_STRB + ch*16, Qbase + row*128 + ch*16);
    }
#pragma unroll
    for (int it = 0; it < 2; ++it) {
        int idx = tid + it*256;
        int row = idx >> 3, ch = idx & 7;
        CP16(sKV + row*AT_STRB + ch*16,            Kbase + row*128 + ch*16);
        CP16(sKV + KV_SMB + row*AT_STRB + ch*16,   Vbase + row*128 + ch*16);
    }
    CP_COMMIT();

    float m0 = -1e30f, m1 = -1e30f, l0 = 0.f, l1 = 0.f;
    float O[8][4];
#pragma unroll
    for (int j = 0; j < 8; ++j)
#pragma unroll
        for (int r = 0; r < 4; ++r) O[j][r] = 0.f;

    uint32_t qf[4][4];

    for (int kt = 0; kt < SEQ/64; ++kt) {
        if (kt + 1 < SEQ/64) {
            const uint32_t dst = sKV + ((kt+1)&1)*(2*KV_SMB);
            const char* Ks = Kbase + (size_t)(kt+1)*64*128;
            const char* Vs = Vbase + (size_t)(kt+1)*64*128;
#pragma unroll
            for (int it = 0; it < 2; ++it) {
                int idx = tid + it*256;
                int row = idx >> 3, ch = idx & 7;
                CP16(dst + row*AT_STRB + ch*16,          Ks + row*128 + ch*16);
                CP16(dst + KV_SMB + row*AT_STRB + ch*16, Vs + row*128 + ch*16);
            }
            CP_COMMIT();
            CP_WAIT(1);
        } else {
            CP_WAIT(0);
        }
        __syncthreads();

        if (kt == 0) {
            const uint32_t qb = sQ + (wid*16 + (lane & 15))*AT_STRB + (lane >> 4)*16;
#pragma unroll
            for (int kk = 0; kk < 4; ++kk)
                LDSM4(qf[kk], qb + kk*32);
        }

        const uint32_t sK = sKV + (kt&1)*(2*KV_SMB);
        const uint32_t sV = sK + KV_SMB;

        // ---- S = Q @ K^T ----
        float c[8][4];
#pragma unroll
        for (int j = 0; j < 8; ++j)
#pragma unroll
            for (int r = 0; r < 4; ++r) c[j][r] = 0.f;

#pragma unroll
        for (int kk = 0; kk < 4; ++kk) {
            const uint32_t kb = sK + (lane & 15)*AT_STRB + (lane >> 4)*16 + kk*32;
#pragma unroll
            for (int j4 = 0; j4 < 4; ++j4) {
                uint32_t b[4];
                LDSM4(b, kb + j4*16*AT_STRB);
                uint32_t bj0[2] = { b[0], b[2] };
                uint32_t bj1[2] = { b[1], b[3] };
                MMA_FP16(c[2*j4],   qf[kk], bj0);
                MMA_FP16(c[2*j4+1], qf[kk], bj1);
            }
        }

        // ---- online softmax ----
        float mx0 = c[0][0], mx1 = c[0][2];
#pragma unroll
        for (int j = 0; j < 8; ++j) {
            mx0 = fmaxf(mx0, fmaxf(c[j][0], c[j][1]));
            mx1 = fmaxf(mx1, fmaxf(c[j][2], c[j][3]));
        }
        mx0 = fmaxf(mx0, __shfl_xor_sync(0xffffffffu, mx0, 1));
        mx0 = fmaxf(mx0, __shfl_xor_sync(0xffffffffu, mx0, 2));
        mx1 = fmaxf(mx1, __shfl_xor_sync(0xffffffffu, mx1, 1));
        mx1 = fmaxf(mx1, __shfl_xor_sync(0xffffffffu, mx1, 2));
        const float mn0 = fmaxf(m0, mx0), mn1 = fmaxf(m1, mx1);
        const float a0 = __expf(m0 - mn0), a1 = __expf(m1 - mn1);
        m0 = mn0; m1 = mn1;

        float s0 = 0.f, s1 = 0.f;
        uint32_t ph[8][2];
#pragma unroll
        for (int j = 0; j < 8; ++j) {
            float p0 = __expf(c[j][0] - m0);
            float p1 = __expf(c[j][1] - m0);
            float p2 = __expf(c[j][2] - m1);
            float p3 = __expf(c[j][3] - m1);
            s0 += p0 + p1;  s1 += p2 + p3;
            __half2 h01 = __floats2half2_rn(p0, p1);
            __half2 h23 = __floats2half2_rn(p2, p3);
            ph[j][0] = *(uint32_t*)&h01;
            ph[j][1] = *(uint32_t*)&h23;
        }
        s0 += __shfl_xor_sync(0xffffffffu, s0, 1);
        s0 += __shfl_xor_sync(0xffffffffu, s0, 2);
        s1 += __shfl_xor_sync(0xffffffffu, s1, 1);
        s1 += __shfl_xor_sync(0xffffffffu, s1, 2);
        l0 = l0*a0 + s0;
        l1 = l1*a1 + s1;
#pragma unroll
        for (int j = 0; j < 8; ++j) {
            O[j][0] *= a0; O[j][1] *= a0;
            O[j][2] *= a1; O[j][3] *= a1;
        }

        // ---- O += P @ V ----
#pragma unroll
        for (int kk = 0; kk < 4; ++kk) {
            uint32_t aP[4] = { ph[2*kk][0], ph[2*kk][1], ph[2*kk+1][0], ph[2*kk+1][1] };
            const uint32_t vb = sV + (16*kk + (lane & 15))*AT_STRB + (lane >> 4)*16;
#pragma unroll
            for (int dn4 = 0; dn4 < 4; ++dn4) {
                uint32_t b[4];
                LDSM4T(b, vb + dn4*32);
                uint32_t b0[2] = { b[0], b[1] };
                uint32_t b1[2] = { b[2], b[3] };
                MMA_FP16(O[2*dn4],   aP, b0);
                MMA_FP16(O[2*dn4+1], aP, b1);
            }
        }
        __syncthreads();
    }

    // ---- epilogue: ctx hi/lo fp16 at [b][q][h*64 + d] ----
    const int b = bh >> 4, h = bh & 15;
    const int q0 = qtile*128 + wid*16 + (lane >> 2);
    const float inv0 = 1.f / l0, inv1 = 1.f / l1;
#pragma unroll
    for (int j = 0; j < 8; ++j) {
        const int col = h*64 + j*8 + (lane & 3)*2;
        float x0 = O[j][0]*inv0, y0 = O[j][1]*inv0;
        float x1 = O[j][2]*inv1, y1 = O[j][3]*inv1;
        __half2 h0 = __floats2half2_rn(x0, y0);
        __half2 h1 = __floats2half2_rn(x1, y1);
        float2 f0 = __half22float2(h0);
        float2 f1 = __half22float2(h1);
        __half2 e0 = __floats2half2_rn(x0 - f0.x, y0 - f0.y);
        __half2 e1 = __floats2half2_rn(x1 - f1.x, y1 - f1.y);
        const size_t r0 = ((size_t)(b*SEQ + q0))*1024 + col;
        const size_t r1 = ((size_t)(b*SEQ + q0 + 8))*1024 + col;
        *(__half2*)(cthi + r0) = h0;
        *(__half2*)(cthi + r1) = h1;
        *(__half2*)(ctlo + r0) = e0;
        *(__half2*)(ctlo + r1) = e1;
    }
}

// =============================================================================
extern "C" void kernel_launch(void* const* d_in, const int* in_sizes, int n_in,
                              void* d_out, int out_size)
{
    (void)in_sizes; (void)n_in; (void)out_size;
    const float* x  = (const float*)d_in[0];
    const float* Wq = (const float*)d_in[1];
    const float* bq = (const float*)d_in[2];
    const float* Wk = (const float*)d_in[3];
    const float* bk = (const float*)d_in[4];
    const float* Wv = (const float*)d_in[5];
    const float* bv = (const float*)d_in[6];
    const float* Wo = (const float*)d_in[7];
    const float* bo = (const float*)d_in[8];
    float* out = (float*)d_out;

    __half *xh, *xl, *wh, *Qp, *Kp, *Vp, *cthi, *ctlo;
    cudaGetSymbolAddress((void**)&xh,   g_xh);
    cudaGetSymbolAddress((void**)&xl,   g_xl);
    cudaGetSymbolAddress((void**)&wh,   g_wh);
    cudaGetSymbolAddress((void**)&Qp,   g_Qh);
    cudaGetSymbolAddress((void**)&Kp,   g_Kh);
    cudaGetSymbolAddress((void**)&Vp,   g_Vh);
    cudaGetSymbolAddress((void**)&cthi, g_cthi);
    cudaGetSymbolAddress((void**)&ctlo, g_ctlo);

    cudaFuncSetAttribute(attn_mma_kernel, cudaFuncAttributeMaxDynamicSharedMemorySize, ATTN_SMEM2);
    cudaFuncSetAttribute(gemm_qkv_mma, cudaFuncAttributeMaxDynamicSharedMemorySize, GEMM_SMEM);
    cudaFuncSetAttribute(gemm_out_mma, cudaFuncAttributeMaxDynamicSharedMemorySize, GEMM_SMEM);

    const int n4x = M_TOTAL*D_MODEL/4;
    const int n4w = D_MODEL*D_MODEL/4;

    split_kernel<<<(n4x+255)/256, 256>>>(x, xh, xl, n4x);
    conv_kernel<<<(n4w+255)/256, 256>>>(Wq, wh + 0*(size_t)D_MODEL*D_MODEL, n4w);
    conv_kernel<<<(n4w+255)/256, 256>>>(Wk, wh + 1*(size_t)D_MODEL*D_MODEL, n4w);
    conv_kernel<<<(n4w+255)/256, 256>>>(Wv, wh + 2*(size_t)D_MODEL*D_MODEL, n4w);
    conv_kernel<<<(n4w+255)/256, 256>>>(Wo, wh + 3*(size_t)D_MODEL*D_MODEL, n4w);

    gemm_qkv_mma<<<dim3(8, 64, 3), 256, GEMM_SMEM>>>(
        xh, xl, wh, bq, bk, bv, Qp, Kp, Vp);

    attn_mma_kernel<<<dim3(SEQ/128, NB*NUM_HEADS), 256, ATTN_SMEM2>>>(Qp, Kp, Vp, cthi, ctlo);

    gemm_out_mma<<<dim3(8, 64, 1), 256, GEMM_SMEM>>>(cthi, ctlo, wh, bo, out);
}

// round 6
// speedup vs baseline: 5.4422x; 1.5695x over previous
#include <cuda_runtime.h>
#include <cuda_fp16.h>
#include <math.h>
#include <stdint.h>

#define D_MODEL 1024
#define NUM_HEADS 16
#define HEAD_DIM 64
#define NB 4
#define SEQ 2048
#define M_TOTAL (NB*SEQ)   // 8192

// ---------------- scratch (device globals: no allocation allowed) -------------
__device__ __half g_xh[M_TOTAL*D_MODEL];     // x (fp16)
__device__ __half g_wh[4*D_MODEL*D_MODEL];   // weights fp16 (q,k,v,o)
__device__ __half g_Qh[NB*NUM_HEADS*SEQ*HEAD_DIM];   // [B,H,S,Hd] pre-scaled
__device__ __half g_Kh[NB*NUM_HEADS*SEQ*HEAD_DIM];
__device__ __half g_Vh[NB*NUM_HEADS*SEQ*HEAD_DIM];
__device__ __half g_ct[M_TOTAL*D_MODEL];     // ctx (fp16) [B,S,D]

// =============================== PTX helpers =================================
__device__ __forceinline__ uint32_t smem_u32(const void* p) {
    uint32_t a;
    asm("{ .reg .u64 t; cvta.to.shared.u64 t, %1; cvt.u32.u64 %0, t; }" : "=r"(a) : "l"(p));
    return a;
}

#define CP16(dst, src) \
    asm volatile("cp.async.cg.shared.global [%0], [%1], 16;" :: "r"(dst), "l"(src))
#define CP_COMMIT() asm volatile("cp.async.commit_group;" ::: "memory")
#define CP_WAIT(N)  asm volatile("cp.async.wait_group %0;" :: "n"(N) : "memory")

#define LDSM4(r, addr) \
    asm volatile("ldmatrix.sync.aligned.m8n8.x4.shared.b16 {%0,%1,%2,%3}, [%4];" \
        : "=r"((r)[0]), "=r"((r)[1]), "=r"((r)[2]), "=r"((r)[3]) : "r"(addr))

#define LDSM4T(r, addr) \
    asm volatile("ldmatrix.sync.aligned.m8n8.x4.trans.shared.b16 {%0,%1,%2,%3}, [%4];" \
        : "=r"((r)[0]), "=r"((r)[1]), "=r"((r)[2]), "=r"((r)[3]) : "r"(addr))

#define MMA_FP16(c, a, b) \
    asm volatile("mma.sync.aligned.m16n8k16.row.col.f32.f16.f16.f32 " \
        "{%0,%1,%2,%3}, {%4,%5,%6,%7}, {%8,%9}, {%0,%1,%2,%3};" \
        : "+f"((c)[0]), "+f"((c)[1]), "+f"((c)[2]), "+f"((c)[3]) \
        : "r"((a)[0]), "r"((a)[1]), "r"((a)[2]), "r"((a)[3]), \
          "r"((b)[0]), "r"((b)[1]))

// =============================================================================
// fp16 mma.sync GEMM: C = A[M,K] @ W[N,K]^T + bias
// BM=BN=128, BK=32, 5-stage cp.async, 8 warps of 64x32 warp tiles.
// smem tile stride 80B (conflict-free ldmatrix). 2 tiles/stage (A, W).
// mode 0: fp16 scatter into [B,H,S,Hd] with scale; mode 1: fp32 row-major.
// =============================================================================
#define TSTR   40
#define TILE_B (128*TSTR*2)       // 10240 B
#define STAGE_B (2*TILE_B)        // 20480 B
#define GSTAGES 5
#define GEMM_SMEM (GSTAGES*STAGE_B)   // 102400 B

__device__ __forceinline__ void gemm_mma_body(
    const __half* __restrict__ A, const __half* __restrict__ W,
    const float* __restrict__ bias, void* __restrict__ Cv, int mode, float oscale)
{
    extern __shared__ char smraw[];
    const uint32_t smb = smem_u32(smraw);
    const int tid  = threadIdx.x;
    const int lane = tid & 31;
    const int wid  = tid >> 5;
    const int wm   = wid & 1;
    const int wn   = wid >> 1;
    const int bm   = blockIdx.y * 128;
    const int bn   = blockIdx.x * 128;

    const int lrow = tid >> 1;
    const int lcol = (tid & 1) * 2;

    const __half* gA0 = A + (size_t)(bm + lrow) * 1024 + lcol * 8;
    const __half* gW0 = W + (size_t)(bn + lrow) * 1024 + lcol * 8;
    const uint32_t dstb = smb + lrow * 80 + lcol * 16;

#define LOAD_STAGE(kt) do { \
        const int _st = (kt) % GSTAGES; \
        const uint32_t _d = dstb + _st * STAGE_B; \
        const int _k0 = (kt) * 32; \
        CP16(_d,            gA0 + _k0); CP16(_d + 16,          gA0 + _k0 + 8); \
        CP16(_d + TILE_B,   gW0 + _k0); CP16(_d + TILE_B + 16, gW0 + _k0 + 8); \
        CP_COMMIT(); \
    } while (0)

    LOAD_STAGE(0);
    LOAD_STAGE(1);
    LOAD_STAGE(2);
    LOAD_STAGE(3);

    float acc[4][4][4];
#pragma unroll
    for (int i = 0; i < 4; ++i)
#pragma unroll
        for (int j = 0; j < 4; ++j)
#pragma unroll
            for (int r = 0; r < 4; ++r) acc[i][j][r] = 0.f;

    const uint32_t a_base = smb + ((wm*64 + (lane & 15)) * TSTR + (lane >> 4) * 8) * 2;
    const uint32_t b_base = smb + TILE_B + ((wn*32 + (lane & 15)) * TSTR + (lane >> 4) * 8) * 2;

    for (int kt = 0; kt < 32; ++kt) {
        if (kt < 28) { CP_WAIT(3); } else { CP_WAIT(0); }
        __syncthreads();
        if (kt + 4 < 32) LOAD_STAGE(kt + 4);

        const uint32_t stoff = (uint32_t)(kt % GSTAGES) * STAGE_B;
#pragma unroll
        for (int kk = 0; kk < 2; ++kk) {
            const uint32_t ko = stoff + kk * 32;
            uint32_t ah[4][4], wf[2][4];
#pragma unroll
            for (int i = 0; i < 4; ++i)
                LDSM4(ah[i], a_base + ko + i*16*80);
#pragma unroll
            for (int j = 0; j < 2; ++j)
                LDSM4(wf[j], b_base + ko + j*16*80);
#pragma unroll
            for (int mi = 0; mi < 4; ++mi)
#pragma unroll
                for (int nj = 0; nj < 4; ++nj) {
                    uint32_t bb[2] = { wf[nj>>1][nj&1], wf[nj>>1][(nj&1)+2] };
                    MMA_FP16(acc[mi][nj], ah[mi], bb);
                }
        }
    }

#pragma unroll
    for (int mi = 0; mi < 4; ++mi) {
#pragma unroll
        for (int nj = 0; nj < 4; ++nj) {
            const int m0 = bm + wm*64 + mi*16 + (lane >> 2);
            const int n0 = bn + wn*32 + nj*8 + (lane & 3)*2;
            float2 bb = *(const float2*)(bias + n0);
            float2 v0, v1;
            v0.x = acc[mi][nj][0] + bb.x;  v0.y = acc[mi][nj][1] + bb.y;
            v1.x = acc[mi][nj][2] + bb.x;  v1.y = acc[mi][nj][3] + bb.y;
            if (mode == 0) {
                __half* Ch = (__half*)Cv;
                const int h = n0 >> 6, hd = n0 & 63;
                const int b0_ = m0 >> 11, s0 = m0 & 2047;
                const int b1_ = (m0+8) >> 11, s1 = (m0+8) & 2047;
                __half2 h0 = __floats2half2_rn(v0.x*oscale, v0.y*oscale);
                __half2 h1 = __floats2half2_rn(v1.x*oscale, v1.y*oscale);
                *(__half2*)(Ch + ((((size_t)(b0_*NUM_HEADS + h) << 11) + s0) << 6) + hd) = h0;
                *(__half2*)(Ch + ((((size_t)(b1_*NUM_HEADS + h) << 11) + s1) << 6) + hd) = h1;
            } else {
                float* C = (float*)Cv;
                *(float2*)(C + (size_t)m0*1024 + n0) = v0;
                *(float2*)(C + (size_t)(m0+8)*1024 + n0) = v1;
            }
        }
    }
#undef LOAD_STAGE
}

__global__ void __launch_bounds__(256, 1)
gemm_qkv_mma(const __half* xh, const __half* wh,
             const float* b0, const float* b1, const float* b2,
             __half* C0, __half* C1, __half* C2)
{
    const int z = blockIdx.z;
    const __half* wz = wh + (size_t)z * D_MODEL * D_MODEL;
    const float* bias = (z == 0) ? b0 : (z == 1) ? b1 : b2;
    __half* C = (z == 0) ? C0 : (z == 1) ? C1 : C2;
    gemm_mma_body(xh, wz, bias, C, 0, (z == 0) ? 0.125f : 1.0f);
}

__global__ void __launch_bounds__(256, 1)
gemm_out_mma(const __half* ct, const __half* wh, const float* bias, float* C)
{
    gemm_mma_body(ct, wh + (size_t)3*D_MODEL*D_MODEL, bias, C, 1, 1.0f);
}

// ===================== fp32 -> fp16 converts ==================================
__global__ void __launch_bounds__(256)
conv_kernel(const float* __restrict__ in, __half* __restrict__ out, int n4)
{
    int i = blockIdx.x * 256 + threadIdx.x;
    if (i >= n4) return;
    float4 v = ((const float4*)in)[i];
    __half2* op = (__half2*)out;
    op[2*i+0] = __floats2half2_rn(v.x, v.y);
    op[2*i+1] = __floats2half2_rn(v.z, v.w);
}

__global__ void __launch_bounds__(256)
conv4_kernel(const float* w0, const float* w1, const float* w2, const float* w3,
             __half* __restrict__ out, int n4)  // n4 per weight
{
    int i = blockIdx.x * 256 + threadIdx.x;
    if (i >= n4) return;
    const float* in = (blockIdx.y == 0) ? w0 : (blockIdx.y == 1) ? w1 :
                      (blockIdx.y == 2) ? w2 : w3;
    float4 v = ((const float4*)in)[i];
    __half2* op = (__half2*)(out + (size_t)blockIdx.y * D_MODEL * D_MODEL);
    op[2*i+0] = __floats2half2_rn(v.x, v.y);
    op[2*i+1] = __floats2half2_rn(v.z, v.w);
}

// =============================================================================
// Tensor-core flash attention (fp16 mma.sync). Epilogue writes ctx fp16.
// CTA: 128 q-rows of one (b,h); 8 warps x 16 rows; 32 key-tiles of 64,
// cp.async double-buffered.
// =============================================================================
#define AT_STRB 144
#define Q_SMB  (128*AT_STRB)
#define KV_SMB (64*AT_STRB)
#define ATTN_SMEM2 (Q_SMB + 4*KV_SMB)

__global__ void __launch_bounds__(256, 2)
attn_mma_kernel(const __half* __restrict__ Qg, const __half* __restrict__ Kg,
                const __half* __restrict__ Vg, __half* __restrict__ ct)
{
    extern __shared__ char smraw[];
    const uint32_t sQ  = smem_u32(smraw);
    const uint32_t sKV = sQ + Q_SMB;
    const int tid  = threadIdx.x;
    const int lane = tid & 31;
    const int wid  = tid >> 5;
    const int qtile = blockIdx.x;
    const int bh    = blockIdx.y;

    const char* Qbase = (const char*)(Qg + (size_t)bh*SEQ*64 + (size_t)qtile*128*64);
    const char* Kbase = (const char*)(Kg + (size_t)bh*SEQ*64);
    const char* Vbase = (const char*)(Vg + (size_t)bh*SEQ*64);

#pragma unroll
    for (int it = 0; it < 4; ++it) {
        int idx = tid + it*256;
        int row = idx >> 3, ch = idx & 7;
        CP16(sQ + row*AT_STRB + ch*16, Qbase + row*128 + ch*16);
    }
#pragma unroll
    for (int it = 0; it < 2; ++it) {
        int idx = tid + it*256;
        int row = idx >> 3, ch = idx & 7;
        CP16(sKV + row*AT_STRB + ch*16,            Kbase + row*128 + ch*16);
        CP16(sKV + KV_SMB + row*AT_STRB + ch*16,   Vbase + row*128 + ch*16);
    }
    CP_COMMIT();

    float m0 = -1e30f, m1 = -1e30f, l0 = 0.f, l1 = 0.f;
    float O[8][4];
#pragma unroll
    for (int j = 0; j < 8; ++j)
#pragma unroll
        for (int r = 0; r < 4; ++r) O[j][r] = 0.f;

    uint32_t qf[4][4];

    for (int kt = 0; kt < SEQ/64; ++kt) {
        if (kt + 1 < SEQ/64) {
            const uint32_t dst = sKV + ((kt+1)&1)*(2*KV_SMB);
            const char* Ks = Kbase + (size_t)(kt+1)*64*128;
            const char* Vs = Vbase + (size_t)(kt+1)*64*128;
#pragma unroll
            for (int it = 0; it < 2; ++it) {
                int idx = tid + it*256;
                int row = idx >> 3, ch = idx & 7;
                CP16(dst + row*AT_STRB + ch*16,          Ks + row*128 + ch*16);
                CP16(dst + KV_SMB + row*AT_STRB + ch*16, Vs + row*128 + ch*16);
            }
            CP_COMMIT();
            CP_WAIT(1);
        } else {
            CP_WAIT(0);
        }
        __syncthreads();

        if (kt == 0) {
            const uint32_t qb = sQ + (wid*16 + (lane & 15))*AT_STRB + (lane >> 4)*16;
#pragma unroll
            for (int kk = 0; kk < 4; ++kk)
                LDSM4(qf[kk], qb + kk*32);
        }

        const uint32_t sK = sKV + (kt&1)*(2*KV_SMB);
        const uint32_t sV = sK + KV_SMB;

        // ---- S = Q @ K^T ----
        float c[8][4];
#pragma unroll
        for (int j = 0; j < 8; ++j)
#pragma unroll
            for (int r = 0; r < 4; ++r) c[j][r] = 0.f;

#pragma unroll
        for (int kk = 0; kk < 4; ++kk) {
            const uint32_t kb = sK + (lane & 15)*AT_STRB + (lane >> 4)*16 + kk*32;
#pragma unroll
            for (int j4 = 0; j4 < 4; ++j4) {
                uint32_t b[4];
                LDSM4(b, kb + j4*16*AT_STRB);
                uint32_t bj0[2] = { b[0], b[2] };
                uint32_t bj1[2] = { b[1], b[3] };
                MMA_FP16(c[2*j4],   qf[kk], bj0);
                MMA_FP16(c[2*j4+1], qf[kk], bj1);
            }
        }

        // ---- online softmax ----
        float mx0 = c[0][0], mx1 = c[0][2];
#pragma unroll
        for (int j = 0; j < 8; ++j) {
            mx0 = fmaxf(mx0, fmaxf(c[j][0], c[j][1]));
            mx1 = fmaxf(mx1, fmaxf(c[j][2], c[j][3]));
        }
        mx0 = fmaxf(mx0, __shfl_xor_sync(0xffffffffu, mx0, 1));
        mx0 = fmaxf(mx0, __shfl_xor_sync(0xffffffffu, mx0, 2));
        mx1 = fmaxf(mx1, __shfl_xor_sync(0xffffffffu, mx1, 1));
        mx1 = fmaxf(mx1, __shfl_xor_sync(0xffffffffu, mx1, 2));
        const float mn0 = fmaxf(m0, mx0), mn1 = fmaxf(m1, mx1);
        const float a0 = __expf(m0 - mn0), a1 = __expf(m1 - mn1);
        m0 = mn0; m1 = mn1;

        float s0 = 0.f, s1 = 0.f;
        uint32_t ph[8][2];
#pragma unroll
        for (int j = 0; j < 8; ++j) {
            float p0 = __expf(c[j][0] - m0);
            float p1 = __expf(c[j][1] - m0);
            float p2 = __expf(c[j][2] - m1);
            float p3 = __expf(c[j][3] - m1);
            s0 += p0 + p1;  s1 += p2 + p3;
            __half2 h01 = __floats2half2_rn(p0, p1);
            __half2 h23 = __floats2half2_rn(p2, p3);
            ph[j][0] = *(uint32_t*)&h01;
            ph[j][1] = *(uint32_t*)&h23;
        }
        s0 += __shfl_xor_sync(0xffffffffu, s0, 1);
        s0 += __shfl_xor_sync(0xffffffffu, s0, 2);
        s1 += __shfl_xor_sync(0xffffffffu, s1, 1);
        s1 += __shfl_xor_sync(0xffffffffu, s1, 2);
        l0 = l0*a0 + s0;
        l1 = l1*a1 + s1;
#pragma unroll
        for (int j = 0; j < 8; ++j) {
            O[j][0] *= a0; O[j][1] *= a0;
            O[j][2] *= a1; O[j][3] *= a1;
        }

        // ---- O += P @ V ----
#pragma unroll
        for (int kk = 0; kk < 4; ++kk) {
            uint32_t aP[4] = { ph[2*kk][0], ph[2*kk][1], ph[2*kk+1][0], ph[2*kk+1][1] };
            const uint32_t vb = sV + (16*kk + (lane & 15))*AT_STRB + (lane >> 4)*16;
#pragma unroll
            for (int dn4 = 0; dn4 < 4; ++dn4) {
                uint32_t b[4];
                LDSM4T(b, vb + dn4*32);
                uint32_t b0[2] = { b[0], b[1] };
                uint32_t b1[2] = { b[2], b[3] };
                MMA_FP16(O[2*dn4],   aP, b0);
                MMA_FP16(O[2*dn4+1], aP, b1);
            }
        }
        __syncthreads();
    }

    // ---- epilogue: ctx fp16 at [b][q][h*64 + d] ----
    const int b = bh >> 4, h = bh & 15;
    const int q0 = qtile*128 + wid*16 + (lane >> 2);
    const float inv0 = 1.f / l0, inv1 = 1.f / l1;
#pragma unroll
    for (int j = 0; j < 8; ++j) {
        const int col = h*64 + j*8 + (lane & 3)*2;
        __half2 h0 = __floats2half2_rn(O[j][0]*inv0, O[j][1]*inv0);
        __half2 h1 = __floats2half2_rn(O[j][2]*inv1, O[j][3]*inv1);
        *(__half2*)(ct + ((size_t)(b*SEQ + q0))*1024 + col) = h0;
        *(__half2*)(ct + ((size_t)(b*SEQ + q0 + 8))*1024 + col) = h1;
    }
}

// =============================================================================
extern "C" void kernel_launch(void* const* d_in, const int* in_sizes, int n_in,
                              void* d_out, int out_size)
{
    (void)in_sizes; (void)n_in; (void)out_size;
    const float* x  = (const float*)d_in[0];
    const float* Wq = (const float*)d_in[1];
    const float* bq = (const float*)d_in[2];
    const float* Wk = (const float*)d_in[3];
    const float* bk = (const float*)d_in[4];
    const float* Wv = (const float*)d_in[5];
    const float* bv = (const float*)d_in[6];
    const float* Wo = (const float*)d_in[7];
    const float* bo = (const float*)d_in[8];
    float* out = (float*)d_out;

    __half *xh, *wh, *Qp, *Kp, *Vp, *ct;
    cudaGetSymbolAddress((void**)&xh, g_xh);
    cudaGetSymbolAddress((void**)&wh, g_wh);
    cudaGetSymbolAddress((void**)&Qp, g_Qh);
    cudaGetSymbolAddress((void**)&Kp, g_Kh);
    cudaGetSymbolAddress((void**)&Vp, g_Vh);
    cudaGetSymbolAddress((void**)&ct, g_ct);

    cudaFuncSetAttribute(attn_mma_kernel, cudaFuncAttributeMaxDynamicSharedMemorySize, ATTN_SMEM2);
    cudaFuncSetAttribute(gemm_qkv_mma, cudaFuncAttributeMaxDynamicSharedMemorySize, GEMM_SMEM);
    cudaFuncSetAttribute(gemm_out_mma, cudaFuncAttributeMaxDynamicSharedMemorySize, GEMM_SMEM);

    const int n4x = M_TOTAL*D_MODEL/4;
    const int n4w = D_MODEL*D_MODEL/4;

    conv_kernel<<<(n4x+255)/256, 256>>>(x, xh, n4x);
    conv4_kernel<<<dim3((n4w+255)/256, 4), 256>>>(Wq, Wk, Wv, Wo, wh, n4w);

    gemm_qkv_mma<<<dim3(8, 64, 3), 256, GEMM_SMEM>>>(
        xh, wh, bq, bk, bv, Qp, Kp, Vp);

    attn_mma_kernel<<<dim3(SEQ/128, NB*NUM_HEADS), 256, ATTN_SMEM2>>>(Qp, Kp, Vp, ct);

    gemm_out_mma<<<dim3(8, 64, 1), 256, GEMM_SMEM>>>(ct, wh, bo, out);
}